// round 13
// baseline (speedup 1.0000x reference)
#include <cuda_runtime.h>
#include <cstdint>
#include <cstddef>

#define N_PTS 8192
#define DIMS  128
#define KNBR  14
#define CAP   896
#define QS    24.0f
#define ROWB  136               // smem panel row stride (bytes), conflict-free
#define PANELB (128 * ROWB)     // 17408 B per 128-row int8 panel
#define NPAIR 2080
#define NBULK 528
#define NMEGA (NPAIR + NBULK)   // 2608

// ---------------- scratch ----------------
__device__ __align__(16) signed char g_XQ[N_PTS * DIMS];   // 1 MB int8, L2-resident
__device__ int       g_SQQ[N_PTS];
__device__ float     g_SQ[N_PTS];
__device__ int       g_THR[N_PTS * 2];
__device__ int       g_CNT[N_PTS];
__device__ long long g_CAND[(size_t)N_PTS * CAP];           // packed (key<<13 | 8191-col)
__device__ double    g_pb[1024];
__device__ double    g_pc[1024];

// ---------------- fast-math ----------------
__device__ __forceinline__ float f_sqrt(float x){ float r; asm("sqrt.approx.f32 %0, %1;" : "=f"(r) : "f"(x)); return r; }
__device__ __forceinline__ float f_rcp (float x){ float r; asm("rcp.approx.f32 %0, %1;"  : "=f"(r) : "f"(x)); return r; }
__device__ __forceinline__ float f_lg2 (float x){ float r; asm("lg2.approx.f32 %0, %1;"  : "=f"(r) : "f"(x)); return r; }
__device__ __forceinline__ float f_ex2 (float x){ float r; asm("ex2.approx.f32 %0, %1;"  : "=f"(r) : "f"(x)); return r; }

#define LN2F   0.69314718055994531f
#define LOG2EF 1.4426950408889634f

__device__ __forceinline__ void cp_async8(uint32_t dst, const void* src) {
    asm volatile("cp.async.ca.shared.global [%0], [%1], 8;" :: "r"(dst), "l"(src));
}

// ---------------- 1) prep ----------------
__global__ void prep_kernel(const float* __restrict__ X) {
    int warp = threadIdx.x >> 5, lane = threadIdx.x & 31;
    int row  = blockIdx.x * 8 + warp;
    const float* xr = X + (size_t)row * DIMS + lane * 4;
    float v0 = xr[0], v1 = xr[1], v2 = xr[2], v3 = xr[3];
    int q0 = __float2int_rn(fminf(fmaxf(v0 * QS, -127.f), 127.f));
    int q1 = __float2int_rn(fminf(fmaxf(v1 * QS, -127.f), 127.f));
    int q2 = __float2int_rn(fminf(fmaxf(v2 * QS, -127.f), 127.f));
    int q3 = __float2int_rn(fminf(fmaxf(v3 * QS, -127.f), 127.f));
    ((int*)g_XQ)[row * 32 + lane] =
        (q0 & 0xff) | ((q1 & 0xff) << 8) | ((q2 & 0xff) << 16) | (q3 << 24);
    float s  = v0*v0 + v1*v1 + v2*v2 + v3*v3;
    int  sq  = q0*q0 + q1*q1 + q2*q2 + q3*q3;
    #pragma unroll
    for (int off = 16; off; off >>= 1) {
        s  += __shfl_xor_sync(0xffffffffu, s,  off);
        sq += __shfl_xor_sync(0xffffffffu, sq, off);
    }
    if (lane == 0) { g_SQ[row] = s; g_SQQ[row] = sq; g_CNT[row] = 0; }
}

// ---------------- dp4a tile core (thread (tx,ty): rows ty*8+j, cols tx+16i) ----------------
__device__ __forceinline__ void tile_dp4a(const char* sA, const char* sB, int tx, int ty,
                                          int acc[8][8]) {
    #pragma unroll
    for (int j = 0; j < 8; j++)
        #pragma unroll
        for (int i = 0; i < 8; i++) acc[j][i] = 0;
    const char* aBase = sA + (ty * 8) * ROWB;
    const char* bBase = sB + tx * ROWB;
    #pragma unroll 4
    for (int p = 0; p < 16; p++) {
        int2 a[8], b[8];
        #pragma unroll
        for (int j = 0; j < 8; j++) a[j] = *(const int2*)(aBase + j * ROWB + p * 8);
        #pragma unroll
        for (int i = 0; i < 8; i++) b[i] = *(const int2*)(bBase + i * 16 * ROWB + p * 8);
        #pragma unroll
        for (int j = 0; j < 8; j++)
            #pragma unroll
            for (int i = 0; i < 8; i++) {
                acc[j][i] = __dp4a(a[j].x, b[i].x, acc[j][i]);
                acc[j][i] = __dp4a(a[j].y, b[i].y, acc[j][i]);
            }
    }
}

// ======================= Phase 1: threshold (1/16 subsample, 2 tiles/block) =======================
#define T_SB   PANELB
#define T_SC   (2 * PANELB)
#define T_ST   (2 * PANELB + 128 * 132 * 4)
#define T_TOT  (T_ST + 256 * KNBR * 4)       // 116736

__global__ __launch_bounds__(256, 1) void thresh_kernel() {
    extern __shared__ __align__(16) char smem[];
    char* sA = smem;
    char* sB = smem + T_SB;
    int*  sSc = (int*)(smem + T_SC);
    int*  stK = (int*)(smem + T_ST);
    __shared__ int sSqqT[128];
    uint32_t sA_u = (uint32_t)__cvta_generic_to_shared(sA);
    uint32_t sB_u = (uint32_t)__cvta_generic_to_shared(sB);

    int tid = threadIdx.x;
    int rb = blockIdx.x >> 1, half = blockIdx.x & 1;
    int rowBlk = rb * 128;
    int tx = tid & 15, ty = tid >> 4;

    #pragma unroll
    for (int i = 0; i < 8; i++) {
        int c = tid + i * 256;
        int r = c >> 4, q = c & 15;
        cp_async8(sA_u + (uint32_t)(r * ROWB + q * 8), g_XQ + (size_t)(rowBlk + r) * DIMS + q * 8);
    }
    asm volatile("cp.async.commit_group;");

    int bk[KNBR];
    #pragma unroll
    for (int s = 0; s < KNBR; s++) bk[s] = (int)0x80000000;
    int srow = tid >> 1, seg = tid & 1;

    for (int t = 0; t < 2; t++) {
        #pragma unroll
        for (int i = 0; i < 8; i++) {
            int c = tid + i * 256;
            int r = c >> 4, q = c & 15;
            int j = 16 * (half * 256 + t * 128 + r);
            cp_async8(sB_u + (uint32_t)(r * ROWB + q * 8), g_XQ + (size_t)j * DIMS + q * 8);
        }
        if (tid < 128) sSqqT[tid] = g_SQQ[16 * (half * 256 + t * 128 + tid)];
        asm volatile("cp.async.commit_group;");
        asm volatile("cp.async.wait_group 0;");
        __syncthreads();

        int acc[8][8];
        tile_dp4a(sA, sB, tx, ty, acc);

        #pragma unroll
        for (int j = 0; j < 8; j++)
            #pragma unroll
            for (int i = 0; i < 8; i++) {
                int col = tx + 16 * i;
                sSc[(ty * 8 + j) * 132 + col] = 2 * acc[j][i] - sSqqT[col];
            }
        __syncthreads();

        const int* prow = sSc + srow * 132 + seg * 64;
        #pragma unroll 8
        for (int c = 0; c < 64; c++) {
            int v = prow[c];
            if (v > bk[KNBR - 1]) {
                int cv = v;
                #pragma unroll
                for (int s = 0; s < KNBR; s++)
                    if (cv > bk[s]) { int tf = bk[s]; bk[s] = cv; cv = tf; }
            }
        }
        __syncthreads();
    }
    #pragma unroll
    for (int s = 0; s < KNBR; s++) stK[tid * KNBR + s] = bk[s];
    __syncthreads();
    if (tid < 128) {
        const int* k0 = stK + (tid * 2) * KNBR;
        const int* k1 = stK + (tid * 2 + 1) * KNBR;
        int p0 = 0, p1 = 0, v = 0;
        #pragma unroll
        for (int s = 0; s < KNBR; s++) {
            if (k0[p0] >= k1[p1]) v = k0[p0++]; else v = k1[p1++];
        }
        g_THR[(rowBlk + tid) * 2 + half] = v;
    }
}

// ======================= Phase 2 mega: filter tiles + bulk tiles, interleaved =======================
__device__ void filter_block(int b) {
    __shared__ __align__(16) char sAbuf[PANELB];
    __shared__ __align__(16) char sBbuf[PANELB];
    __shared__ int sTI[128], sSqI[128], sTJ[128], sSqJ[128];
    uint32_t sA_u = (uint32_t)__cvta_generic_to_shared(sAbuf);
    uint32_t sB_u = (uint32_t)__cvta_generic_to_shared(sBbuf);

    int tid = threadIdx.x;
    int tx = tid & 15, ty = tid >> 4;

    int I = (int)floorf(64.5f - f_sqrt(64.5f * 64.5f - 2.0f * (float)b));
    while (64 * (I + 1) - ((I + 1) * I) / 2 <= b) I++;
    while (64 * I - (I * (I - 1)) / 2 > b) I--;
    int J = I + (b - (64 * I - (I * (I - 1)) / 2));
    int Ibase = I * 128, Jbase = J * 128;

    #pragma unroll
    for (int i = 0; i < 8; i++) {
        int c = tid + i * 256;
        int r = c >> 4, q = c & 15;
        cp_async8(sA_u + (uint32_t)(r * ROWB + q * 8), g_XQ + (size_t)(Ibase + r) * DIMS + q * 8);
        cp_async8(sB_u + (uint32_t)(r * ROWB + q * 8), g_XQ + (size_t)(Jbase + r) * DIMS + q * 8);
    }
    asm volatile("cp.async.commit_group;");
    if (tid < 128) {
        int r = Ibase + tid;
        int t0 = g_THR[r * 2], t1 = g_THR[r * 2 + 1];
        sTI[tid] = (t0 > t1) ? t0 : t1;
        sSqI[tid] = g_SQQ[r];
    } else {
        int r = Jbase + (tid - 128);
        int t0 = g_THR[r * 2], t1 = g_THR[r * 2 + 1];
        sTJ[tid - 128] = (t0 > t1) ? t0 : t1;
        sSqJ[tid - 128] = g_SQQ[r];
    }
    asm volatile("cp.async.wait_group 0;");
    __syncthreads();

    int acc[8][8];
    tile_dp4a(sAbuf, sBbuf, tx, ty, acc);

    int TI[8], sqI[8], TJ[8], sqJ[8];
    #pragma unroll
    for (int j = 0; j < 8; j++) { TI[j] = sTI[ty * 8 + j]; sqI[j] = sSqI[ty * 8 + j]; }
    #pragma unroll
    for (int i = 0; i < 8; i++) { TJ[i] = sTJ[tx + 16 * i]; sqJ[i] = sSqJ[tx + 16 * i]; }

    int minSqJ = sqJ[0], minSqI = sqI[0];
    #pragma unroll
    for (int i = 1; i < 8; i++) if (sqJ[i] < minSqJ) minSqJ = sqJ[i];
    #pragma unroll
    for (int j = 1; j < 8; j++) if (sqI[j] < minSqI) minSqI = sqI[j];

    #pragma unroll
    for (int j = 0; j < 8; j++) {
        int mv = acc[j][0];
        #pragma unroll
        for (int i = 1; i < 8; i++) if (acc[j][i] > mv) mv = acc[j][i];
        if (2 * mv - minSqJ >= TI[j]) {
            int row = Ibase + ty * 8 + j;
            #pragma unroll
            for (int i = 0; i < 8; i++) {
                int key = 2 * acc[j][i] - sqJ[i];
                if (key >= TI[j]) {
                    int col = Jbase + tx + 16 * i;
                    int pos = atomicAdd(&g_CNT[row], 1);
                    if (pos < CAP)
                        g_CAND[(size_t)row * CAP + pos] =
                            ((long long)key << 13) | (long long)(8191 - col);
                }
            }
        }
    }
    if (I != J) {
        #pragma unroll
        for (int i = 0; i < 8; i++) {
            int mv = acc[0][i];
            #pragma unroll
            for (int j = 1; j < 8; j++) if (acc[j][i] > mv) mv = acc[j][i];
            if (2 * mv - minSqI >= TJ[i]) {
                int row = Jbase + tx + 16 * i;
                #pragma unroll
                for (int j = 0; j < 8; j++) {
                    int key = 2 * acc[j][i] - sqI[j];
                    if (key >= TJ[i]) {
                        int col = Ibase + ty * 8 + j;
                        int pos = atomicAdd(&g_CNT[row], 1);
                        if (pos < CAP)
                            g_CAND[(size_t)row * CAP + pos] =
                                ((long long)key << 13) | (long long)(8191 - col);
                    }
                }
            }
        }
    }
}

__device__ void bulk_block(int b, const float* __restrict__ LO) {
    int i = (int)(32.5f - f_sqrt(32.5f * 32.5f - 2.0f * (float)b));
    while ((i + 1) * 32 - ((i + 1) * i) / 2 <= b) i++;
    while (i * 32 - (i * (i - 1)) / 2 > b) i--;
    int j = i + (b - (i * 32 - (i * (i - 1)) / 2));
    int ibase = i * 256, jbase = j * 256;

    __shared__ float2 sLo[256];
    __shared__ double sred[256];
    int tid = threadIdx.x;
    const float2* lo2 = (const float2*)LO;
    int gi = ibase + tid;
    float2 me = lo2[gi];
    sLo[tid] = lo2[jbase + tid];
    __syncthreads();

    float accf = 0.f;
    if (j > i) {
        #pragma unroll 4
        for (int c = 0; c < 256; c++) {
            float2 o = sLo[c];
            float dx = me.x - o.x, dy = me.y - o.y;
            float d = f_sqrt(fmaf(dx, dx, dy * dy));
            float r = f_rcp(1.0f + d);
            accf += f_lg2((1.0f - r) + 1e-10f);
        }
        accf *= 2.0f;
    } else {
        #pragma unroll 4
        for (int c = 0; c < 256; c++) {
            int jg = jbase + c;
            float2 o = sLo[c];
            float dx = me.x - o.x, dy = me.y - o.y;
            float d = f_sqrt(fmaf(dx, dx, dy * dy));
            float r = f_rcp(1.0f + d);
            float term = f_lg2((1.0f - r) + 1e-10f);
            float w = (jg > gi) ? 2.0f : ((jg == gi) ? 1.0f : 0.0f);
            accf += w * term;
        }
    }
    sred[tid] = (double)(accf * LN2F);
    __syncthreads();
    for (int off = 128; off; off >>= 1) { if (tid < off) sred[tid] += sred[tid + off]; __syncthreads(); }
    if (tid == 0) g_pb[b] = sred[0];
}

__global__ __launch_bounds__(256, 2) void mega_kernel(const float* __restrict__ LO) {
    int b = blockIdx.x;
    int nb0 = (int)(((long long)b * NBULK) / NMEGA);
    int nb1 = (int)(((long long)(b + 1) * NBULK) / NMEGA);
    if (nb1 > nb0) bulk_block(nb0, LO);      // Bresenham-interleaved bulk blocks
    else           filter_block(b - nb0);
}

// ======================= Phase 3: fused select + corr (warp per row) =======================
__global__ void selcorr_kernel(const float* __restrict__ X, const float* __restrict__ LO) {
    __shared__ double wsum[8];
    int warp = threadIdx.x >> 5, lane = threadIdx.x & 31;
    int row  = blockIdx.x * 8 + warp;
    int cnt = g_CNT[row]; if (cnt > CAP) cnt = CAP;
    const long long* cand = g_CAND + (size_t)row * CAP;
    const long long MINV = 0x8000000000000000LL;

    long long bk[KNBR];
    #pragma unroll
    for (int s = 0; s < KNBR; s++) bk[s] = MINV;
    for (int c = lane; c < cnt; c += 32) {
        long long v = cand[c];
        if (v > bk[KNBR - 1]) {
            long long cv = v;
            #pragma unroll
            for (int s = 0; s < KNBR; s++)
                if (cv > bk[s]) { long long tf = bk[s]; bk[s] = cv; cv = tf; }
        }
    }

    // corr state
    const float* xi = X + (size_t)row * DIMS;
    float a0 = xi[lane], a1 = xi[lane + 32], a2 = xi[lane + 64], a3 = xi[lane + 96];
    const float2* lo2 = (const float2*)LO;
    float2 li = lo2[row];
    float sqi = g_SQ[row];
    float acc = 0.f;

    for (int r = 0; r < KNBR; r++) {
        long long m = bk[0];
        int owner = lane;
        #pragma unroll
        for (int off = 16; off; off >>= 1) {
            long long ov = __shfl_xor_sync(0xffffffffu, m, off);
            int       ow = __shfl_xor_sync(0xffffffffu, owner, off);
            if (ov > m) { m = ov; owner = ow; }
        }
        if (lane == owner) {
            #pragma unroll
            for (int s = 0; s < KNBR - 1; s++) bk[s] = bk[s + 1];
            bk[KNBR - 1] = MINV;
        }
        int j = 8191 - (int)(m & 8191);

        const float* xj = X + (size_t)j * DIMS;
        float dot = a0 * xj[lane] + a1 * xj[lane + 32] + a2 * xj[lane + 64] + a3 * xj[lane + 96];
        #pragma unroll
        for (int off = 16; off; off >>= 1) dot += __shfl_xor_sync(0xffffffffu, dot, off);
        float d2h = fmaxf(sqi + g_SQ[j] - 2.f * dot, 0.f);
        float hd = f_sqrt(d2h);
        float hs = f_ex2(-LOG2EF * hd);
        float2 lj = lo2[j];
        float dx = li.x - lj.x, dy = li.y - lj.y;
        float ld = f_sqrt(fmaf(dx, dx, dy * dy));
        float rr = f_rcp(1.0f + ld);
        float A  = hs * (f_lg2(rr + 1e-10f) * LN2F);
        float Bs = f_lg2((1.0f - rr) + 1e-10f) * LN2F;
        acc += (A - Bs);
    }
    if (lane == 0) wsum[warp] = (double)acc;
    __syncthreads();
    if (threadIdx.x == 0) {
        double s = 0;
        for (int k = 0; k < 8; k++) s += wsum[k];
        g_pc[blockIdx.x] = s;
    }
}

// ---------------- deterministic final reduce ----------------
__global__ void final_kernel(float* __restrict__ out) {
    __shared__ double sred[256];
    int t = threadIdx.x;
    double s = 0;
    for (int k = t; k < 528;  k += 256) s += g_pb[k];
    for (int k = t; k < 1024; k += 256) s += g_pc[k];
    sred[t] = s;
    __syncthreads();
    for (int off = 128; off; off >>= 1) { if (t < off) sred[t] += sred[t + off]; __syncthreads(); }
    if (t == 0) out[0] = (float)(-(sred[0] / 67108864.0) * 100.0);
}

// ---------------- launch ----------------
extern "C" void kernel_launch(void* const* d_in, const int* in_sizes, int n_in,
                              void* d_out, int out_size) {
    const float* X; const float* LO;
    if (in_sizes[0] == N_PTS * DIMS) { X = (const float*)d_in[0]; LO = (const float*)d_in[1]; }
    else                             { X = (const float*)d_in[1]; LO = (const float*)d_in[0]; }

    cudaFuncSetAttribute(thresh_kernel, cudaFuncAttributeMaxDynamicSharedMemorySize, T_TOT);

    prep_kernel   <<<N_PTS / 8, 256>>>(X);
    thresh_kernel <<<128, 256, T_TOT>>>();
    mega_kernel   <<<NMEGA, 256>>>(LO);
    selcorr_kernel<<<N_PTS / 8, 256>>>(X, LO);
    final_kernel  <<<1, 256>>>((float*)d_out);
}

// round 14
// speedup vs baseline: 1.1850x; 1.1850x over previous
#include <cuda_runtime.h>
#include <cstdint>
#include <cstddef>

#define N_PTS 8192
#define DIMS  128
#define KNBR  14
#define CAP   448
#define QS    24.0f
#define ROWB  136               // smem panel row stride (bytes): conflict-free int2 LDS
#define PANELB (128 * ROWB)     // 17408 B per 128-row int8 panel
#define NPAIR 2080
#define NBULK 528

// ---------------- scratch ----------------
__device__ __align__(16) signed char g_XQ[N_PTS * DIMS];   // 1 MB int8, L2-resident
__device__ int       g_SQQ[N_PTS];                          // |q_i|^2 exact int
__device__ float     g_SQ[N_PTS];                           // fp32 row norms (for corr)
__device__ int       g_THR[N_PTS * 2];
__device__ int       g_CNT[N_PTS];
__device__ long long g_CAND[(size_t)N_PTS * CAP];           // packed (key<<13 | 8191-col)
__device__ int       g_NBR[N_PTS * KNBR];
__device__ double    g_pb[1024];
__device__ double    g_pc[1024];

// ---------------- fast-math ----------------
__device__ __forceinline__ float f_sqrt(float x){ float r; asm("sqrt.approx.f32 %0, %1;" : "=f"(r) : "f"(x)); return r; }
__device__ __forceinline__ float f_rcp (float x){ float r; asm("rcp.approx.f32 %0, %1;"  : "=f"(r) : "f"(x)); return r; }
__device__ __forceinline__ float f_lg2 (float x){ float r; asm("lg2.approx.f32 %0, %1;"  : "=f"(r) : "f"(x)); return r; }
__device__ __forceinline__ float f_ex2 (float x){ float r; asm("ex2.approx.f32 %0, %1;"  : "=f"(r) : "f"(x)); return r; }

#define LN2F   0.69314718055994531f
#define LOG2EF 1.4426950408889634f

__device__ __forceinline__ void cp_async8(uint32_t dst, const void* src) {
    asm volatile("cp.async.ca.shared.global [%0], [%1], 8;" :: "r"(dst), "l"(src));
}

// ---------------- 1) prep: quantize + norms + counter reset ----------------
__global__ void prep_kernel(const float* __restrict__ X) {
    int warp = threadIdx.x >> 5, lane = threadIdx.x & 31;
    int row  = blockIdx.x * 8 + warp;
    const float* xr = X + (size_t)row * DIMS + lane * 4;
    float v0 = xr[0], v1 = xr[1], v2 = xr[2], v3 = xr[3];
    int q0 = __float2int_rn(fminf(fmaxf(v0 * QS, -127.f), 127.f));
    int q1 = __float2int_rn(fminf(fmaxf(v1 * QS, -127.f), 127.f));
    int q2 = __float2int_rn(fminf(fmaxf(v2 * QS, -127.f), 127.f));
    int q3 = __float2int_rn(fminf(fmaxf(v3 * QS, -127.f), 127.f));
    ((int*)g_XQ)[row * 32 + lane] =
        (q0 & 0xff) | ((q1 & 0xff) << 8) | ((q2 & 0xff) << 16) | (q3 << 24);
    float s  = v0*v0 + v1*v1 + v2*v2 + v3*v3;
    int  sq  = q0*q0 + q1*q1 + q2*q2 + q3*q3;
    #pragma unroll
    for (int off = 16; off; off >>= 1) {
        s  += __shfl_xor_sync(0xffffffffu, s,  off);
        sq += __shfl_xor_sync(0xffffffffu, sq, off);
    }
    if (lane == 0) { g_SQ[row] = s; g_SQQ[row] = sq; g_CNT[row] = 0; }
}

// ---------------- dp4a tile core: thread (tx,ty) owns rows ty*8+j, cols tx+16i ----------------
__device__ __forceinline__ void tile_dp4a(const char* sA, const char* sB, int tx, int ty,
                                          int acc[8][8]) {
    #pragma unroll
    for (int j = 0; j < 8; j++)
        #pragma unroll
        for (int i = 0; i < 8; i++) acc[j][i] = 0;
    const char* aBase = sA + (ty * 8) * ROWB;
    const char* bBase = sB + tx * ROWB;
    #pragma unroll 4
    for (int p = 0; p < 16; p++) {
        int2 a[8], b[8];
        #pragma unroll
        for (int j = 0; j < 8; j++) a[j] = *(const int2*)(aBase + j * ROWB + p * 8);
        #pragma unroll
        for (int i = 0; i < 8; i++) b[i] = *(const int2*)(bBase + i * 16 * ROWB + p * 8);
        #pragma unroll
        for (int j = 0; j < 8; j++)
            #pragma unroll
            for (int i = 0; i < 8; i++) {
                acc[j][i] = __dp4a(a[j].x, b[i].x, acc[j][i]);
                acc[j][i] = __dp4a(a[j].y, b[i].y, acc[j][i]);
            }
    }
}

// ======================= Phase 1: per-(row, half) threshold (1/8 subsample) =======================
#define T_SB   PANELB
#define T_SC   (2 * PANELB)
#define T_ST   (2 * PANELB + 128 * 132 * 4)
#define T_TOT  (T_ST + 256 * KNBR * 4)       // 116736

__global__ __launch_bounds__(256, 1) void thresh_kernel() {
    extern __shared__ __align__(16) char smem[];
    char* sA = smem;
    char* sB = smem + T_SB;
    int*  sSc = (int*)(smem + T_SC);
    int*  stK = (int*)(smem + T_ST);
    __shared__ int sSqqT[128];
    uint32_t sA_u = (uint32_t)__cvta_generic_to_shared(sA);
    uint32_t sB_u = (uint32_t)__cvta_generic_to_shared(sB);

    int tid = threadIdx.x;
    int rb = blockIdx.x >> 1, half = blockIdx.x & 1;
    int rowBlk = rb * 128;
    int tx = tid & 15, ty = tid >> 4;

    #pragma unroll
    for (int i = 0; i < 8; i++) {
        int c = tid + i * 256;
        int r = c >> 4, q = c & 15;
        cp_async8(sA_u + (uint32_t)(r * ROWB + q * 8), g_XQ + (size_t)(rowBlk + r) * DIMS + q * 8);
    }
    asm volatile("cp.async.commit_group;");

    int bk[KNBR];
    #pragma unroll
    for (int s = 0; s < KNBR; s++) bk[s] = (int)0x80000000;
    int srow = tid >> 1, seg = tid & 1;

    for (int t = 0; t < 4; t++) {
        #pragma unroll
        for (int i = 0; i < 8; i++) {
            int c = tid + i * 256;
            int r = c >> 4, q = c & 15;
            int j = 8 * (half * 512 + t * 128 + r);
            cp_async8(sB_u + (uint32_t)(r * ROWB + q * 8), g_XQ + (size_t)j * DIMS + q * 8);
        }
        if (tid < 128) sSqqT[tid] = g_SQQ[8 * (half * 512 + t * 128 + tid)];
        asm volatile("cp.async.commit_group;");
        asm volatile("cp.async.wait_group 0;");
        __syncthreads();

        int acc[8][8];
        tile_dp4a(sA, sB, tx, ty, acc);

        #pragma unroll
        for (int j = 0; j < 8; j++)
            #pragma unroll
            for (int i = 0; i < 8; i++) {
                int col = tx + 16 * i;
                sSc[(ty * 8 + j) * 132 + col] = 2 * acc[j][i] - sSqqT[col];
            }
        __syncthreads();

        const int* prow = sSc + srow * 132 + seg * 64;
        #pragma unroll 8
        for (int c = 0; c < 64; c++) {
            int v = prow[c];
            if (v > bk[KNBR - 1]) {
                int cv = v;
                #pragma unroll
                for (int s = 0; s < KNBR; s++)
                    if (cv > bk[s]) { int tf = bk[s]; bk[s] = cv; cv = tf; }
            }
        }
        __syncthreads();
    }
    #pragma unroll
    for (int s = 0; s < KNBR; s++) stK[tid * KNBR + s] = bk[s];
    __syncthreads();
    if (tid < 128) {
        const int* k0 = stK + (tid * 2) * KNBR;
        const int* k1 = stK + (tid * 2 + 1) * KNBR;
        int p0 = 0, p1 = 0, v = 0;
        #pragma unroll
        for (int s = 0; s < KNBR; s++) {
            if (k0[p0] >= k1[p1]) v = k0[p0++]; else v = k1[p1++];
        }
        g_THR[(rowBlk + tid) * 2 + half] = v;
    }
}

// ======================= Phase 2: symmetric dp4a GEMM + filter =======================
__global__ __launch_bounds__(256, 2) void filter_kernel() {
    __shared__ __align__(16) char sAbuf[PANELB];
    __shared__ __align__(16) char sBbuf[PANELB];
    __shared__ int sTI[128], sSqI[128], sTJ[128], sSqJ[128];
    uint32_t sA_u = (uint32_t)__cvta_generic_to_shared(sAbuf);
    uint32_t sB_u = (uint32_t)__cvta_generic_to_shared(sBbuf);

    int tid = threadIdx.x;
    int tx = tid & 15, ty = tid >> 4;

    int b = blockIdx.x;
    int I = (int)floorf(64.5f - f_sqrt(64.5f * 64.5f - 2.0f * (float)b));
    while (64 * (I + 1) - ((I + 1) * I) / 2 <= b) I++;
    while (64 * I - (I * (I - 1)) / 2 > b) I--;
    int J = I + (b - (64 * I - (I * (I - 1)) / 2));
    int Ibase = I * 128, Jbase = J * 128;

    #pragma unroll
    for (int i = 0; i < 8; i++) {
        int c = tid + i * 256;
        int r = c >> 4, q = c & 15;
        cp_async8(sA_u + (uint32_t)(r * ROWB + q * 8), g_XQ + (size_t)(Ibase + r) * DIMS + q * 8);
        cp_async8(sB_u + (uint32_t)(r * ROWB + q * 8), g_XQ + (size_t)(Jbase + r) * DIMS + q * 8);
    }
    asm volatile("cp.async.commit_group;");
    if (tid < 128) {
        int r = Ibase + tid;
        int t0 = g_THR[r * 2], t1 = g_THR[r * 2 + 1];
        sTI[tid] = (t0 > t1) ? t0 : t1;
        sSqI[tid] = g_SQQ[r];
    } else {
        int r = Jbase + (tid - 128);
        int t0 = g_THR[r * 2], t1 = g_THR[r * 2 + 1];
        sTJ[tid - 128] = (t0 > t1) ? t0 : t1;
        sSqJ[tid - 128] = g_SQQ[r];
    }
    asm volatile("cp.async.wait_group 0;");
    __syncthreads();

    int acc[8][8];
    tile_dp4a(sAbuf, sBbuf, tx, ty, acc);

    int TI[8], sqI[8], TJ[8], sqJ[8];
    #pragma unroll
    for (int j = 0; j < 8; j++) { TI[j] = sTI[ty * 8 + j]; sqI[j] = sSqI[ty * 8 + j]; }
    #pragma unroll
    for (int i = 0; i < 8; i++) { TJ[i] = sTJ[tx + 16 * i]; sqJ[i] = sSqJ[tx + 16 * i]; }

    int minSqJ = sqJ[0], minSqI = sqI[0];
    #pragma unroll
    for (int i = 1; i < 8; i++) if (sqJ[i] < minSqJ) minSqJ = sqJ[i];
    #pragma unroll
    for (int j = 1; j < 8; j++) if (sqI[j] < minSqI) minSqI = sqI[j];

    #pragma unroll
    for (int j = 0; j < 8; j++) {
        int mv = acc[j][0];
        #pragma unroll
        for (int i = 1; i < 8; i++) if (acc[j][i] > mv) mv = acc[j][i];
        if (2 * mv - minSqJ >= TI[j]) {
            int row = Ibase + ty * 8 + j;
            #pragma unroll
            for (int i = 0; i < 8; i++) {
                int key = 2 * acc[j][i] - sqJ[i];
                if (key >= TI[j]) {
                    int col = Jbase + tx + 16 * i;
                    int pos = atomicAdd(&g_CNT[row], 1);
                    if (pos < CAP)
                        g_CAND[(size_t)row * CAP + pos] =
                            ((long long)key << 13) | (long long)(8191 - col);
                }
            }
        }
    }
    if (I != J) {
        #pragma unroll
        for (int i = 0; i < 8; i++) {
            int mv = acc[0][i];
            #pragma unroll
            for (int j = 1; j < 8; j++) if (acc[j][i] > mv) mv = acc[j][i];
            if (2 * mv - minSqI >= TJ[i]) {
                int row = Jbase + tx + 16 * i;
                #pragma unroll
                for (int j = 0; j < 8; j++) {
                    int key = 2 * acc[j][i] - sqI[j];
                    if (key >= TJ[i]) {
                        int col = Ibase + ty * 8 + j;
                        int pos = atomicAdd(&g_CNT[row], 1);
                        if (pos < CAP)
                            g_CAND[(size_t)row * CAP + pos] =
                                ((long long)key << 13) | (long long)(8191 - col);
                    }
                }
            }
        }
    }
}

// ======================= Phase 3: warp-per-row top-14 =======================
__global__ void select_topk() {
    int warp = threadIdx.x >> 5, lane = threadIdx.x & 31;
    int row  = blockIdx.x * 8 + warp;
    int cnt = g_CNT[row]; if (cnt > CAP) cnt = CAP;
    const long long* cand = g_CAND + (size_t)row * CAP;
    const long long MINV = 0x8000000000000000LL;

    long long bk[KNBR];
    #pragma unroll
    for (int s = 0; s < KNBR; s++) bk[s] = MINV;
    for (int c = lane; c < cnt; c += 32) {
        long long v = cand[c];
        if (v > bk[KNBR - 1]) {
            long long cv = v;
            #pragma unroll
            for (int s = 0; s < KNBR; s++)
                if (cv > bk[s]) { long long tf = bk[s]; bk[s] = cv; cv = tf; }
        }
    }
    for (int r = 0; r < KNBR; r++) {
        long long m = bk[0];
        int owner = lane;
        #pragma unroll
        for (int off = 16; off; off >>= 1) {
            long long ov = __shfl_xor_sync(0xffffffffu, m, off);
            int       ow = __shfl_xor_sync(0xffffffffu, owner, off);
            if (ov > m) { m = ov; owner = ow; }
        }
        if (lane == owner) {
            #pragma unroll
            for (int s = 0; s < KNBR - 1; s++) bk[s] = bk[s + 1];
            bk[KNBR - 1] = MINV;
        }
        if (lane == 0) g_NBR[row * KNBR + r] = 8191 - (int)(m & 8191);
    }
}

// ---------------- bulk lo-dim loss: exact triangular grid ----------------
__global__ void bulk_kernel(const float* __restrict__ LO) {
    int b = blockIdx.x;
    int i = (int)(32.5f - f_sqrt(32.5f * 32.5f - 2.0f * (float)b));
    while ((i + 1) * 32 - ((i + 1) * i) / 2 <= b) i++;
    while (i * 32 - (i * (i - 1)) / 2 > b) i--;
    int j = i + (b - (i * 32 - (i * (i - 1)) / 2));
    int ibase = i * 256, jbase = j * 256;

    __shared__ float2 sLo[256];
    __shared__ double sred[256];
    int tid = threadIdx.x;
    const float2* lo2 = (const float2*)LO;
    int gi = ibase + tid;
    float2 me = lo2[gi];
    sLo[tid] = lo2[jbase + tid];
    __syncthreads();

    float accf = 0.f;
    if (j > i) {
        #pragma unroll 4
        for (int c = 0; c < 256; c++) {
            float2 o = sLo[c];
            float dx = me.x - o.x, dy = me.y - o.y;
            float d = f_sqrt(fmaf(dx, dx, dy * dy));
            float r = f_rcp(1.0f + d);
            accf += f_lg2((1.0f - r) + 1e-10f);
        }
        accf *= 2.0f;
    } else {
        #pragma unroll 4
        for (int c = 0; c < 256; c++) {
            int jg = jbase + c;
            float2 o = sLo[c];
            float dx = me.x - o.x, dy = me.y - o.y;
            float d = f_sqrt(fmaf(dx, dx, dy * dy));
            float r = f_rcp(1.0f + d);
            float term = f_lg2((1.0f - r) + 1e-10f);
            float w = (jg > gi) ? 2.0f : ((jg == gi) ? 1.0f : 0.0f);
            accf += w * term;
        }
    }
    sred[tid] = (double)(accf * LN2F);
    __syncthreads();
    for (int off = 128; off; off >>= 1) { if (tid < off) sred[tid] += sred[tid + off]; __syncthreads(); }
    if (tid == 0) g_pb[b] = sred[0];
}

// ---------------- exact neighbor correction ----------------
__global__ void corr_kernel(const float* __restrict__ X, const float* __restrict__ LO) {
    __shared__ double wsum[8];
    int warp = threadIdx.x >> 5, lane = threadIdx.x & 31;
    int row  = blockIdx.x * 8 + warp;
    const float* xi = X + (size_t)row * DIMS;
    float a0 = xi[lane], a1 = xi[lane + 32], a2 = xi[lane + 64], a3 = xi[lane + 96];
    const float2* lo2 = (const float2*)LO;
    float2 li = lo2[row];
    float sqi = g_SQ[row];

    float acc = 0.f;
    for (int n = 0; n < KNBR; n++) {
        int j = g_NBR[row * KNBR + n];
        const float* xj = X + (size_t)j * DIMS;
        float dot = a0 * xj[lane] + a1 * xj[lane + 32] + a2 * xj[lane + 64] + a3 * xj[lane + 96];
        #pragma unroll
        for (int off = 16; off; off >>= 1) dot += __shfl_xor_sync(0xffffffffu, dot, off);
        float d2h = fmaxf(sqi + g_SQ[j] - 2.f * dot, 0.f);
        float hd = f_sqrt(d2h);
        float hs = f_ex2(-LOG2EF * hd);
        float2 lj = lo2[j];
        float dx = li.x - lj.x, dy = li.y - lj.y;
        float ld = f_sqrt(fmaf(dx, dx, dy * dy));
        float r  = f_rcp(1.0f + ld);
        float A  = hs * (f_lg2(r + 1e-10f) * LN2F);
        float Bs = f_lg2((1.0f - r) + 1e-10f) * LN2F;
        acc += (A - Bs);
    }
    if (lane == 0) wsum[warp] = (double)acc;
    __syncthreads();
    if (threadIdx.x == 0) {
        double s = 0;
        for (int k = 0; k < 8; k++) s += wsum[k];
        g_pc[blockIdx.x] = s;
    }
}

// ---------------- deterministic final reduce ----------------
__global__ void final_kernel(float* __restrict__ out) {
    __shared__ double sred[256];
    int t = threadIdx.x;
    double s = 0;
    for (int k = t; k < 528;  k += 256) s += g_pb[k];
    for (int k = t; k < 1024; k += 256) s += g_pc[k];
    sred[t] = s;
    __syncthreads();
    for (int off = 128; off; off >>= 1) { if (t < off) sred[t] += sred[t + off]; __syncthreads(); }
    if (t == 0) out[0] = (float)(-(sred[0] / 67108864.0) * 100.0);
}

// ---------------- launch: bulk forked onto a side stream, joined before final ----------------
extern "C" void kernel_launch(void* const* d_in, const int* in_sizes, int n_in,
                              void* d_out, int out_size) {
    const float* X; const float* LO;
    if (in_sizes[0] == N_PTS * DIMS) { X = (const float*)d_in[0]; LO = (const float*)d_in[1]; }
    else                             { X = (const float*)d_in[1]; LO = (const float*)d_in[0]; }

    cudaFuncSetAttribute(thresh_kernel, cudaFuncAttributeMaxDynamicSharedMemorySize, T_TOT);

    cudaStream_t s2;
    cudaEvent_t eFork, eJoin;
    cudaStreamCreateWithFlags(&s2, cudaStreamNonBlocking);
    cudaEventCreateWithFlags(&eFork, cudaEventDisableTiming);
    cudaEventCreateWithFlags(&eJoin, cudaEventDisableTiming);

    prep_kernel  <<<N_PTS / 8, 256>>>(X);

    // fork: bulk (depends only on LO) runs concurrently with thresh+filter
    cudaEventRecord(eFork, 0);
    cudaStreamWaitEvent(s2, eFork, 0);
    bulk_kernel  <<<NBULK, 256, 0, s2>>>(LO);

    thresh_kernel<<<128, 256, T_TOT>>>();
    filter_kernel<<<NPAIR, 256>>>();
    select_topk  <<<N_PTS / 8, 256>>>();
    corr_kernel  <<<N_PTS / 8, 256>>>(X, LO);

    // join: final needs bulk partials
    cudaEventRecord(eJoin, s2);
    cudaStreamWaitEvent(0, eJoin, 0);
    final_kernel <<<1, 256>>>((float*)d_out);

    cudaEventDestroy(eFork);
    cudaEventDestroy(eJoin);
    cudaStreamDestroy(s2);
}

// round 15
// speedup vs baseline: 1.3709x; 1.1568x over previous
#include <cuda_runtime.h>
#include <cstdint>
#include <cstddef>

#define N_PTS 8192
#define DIMS  128
#define KNBR  14
#define CAP   448
#define QS    24.0f
#define ROWB  136               // smem panel row stride (bytes): conflict-free int2 LDS
#define PANELB  (128 * ROWB)    // 17408 B per 128-row int8 panel
#define HPANELB (64 * ROWB)     // 8704 B per 64-row half panel
#define NPAIR 2080
#define NBULK 528

// ---------------- scratch ----------------
__device__ __align__(16) signed char g_XQ[N_PTS * DIMS];   // 1 MB int8, L2-resident
__device__ int       g_SQQ[N_PTS];                          // |q_i|^2 exact int
__device__ float     g_SQ[N_PTS];                           // fp32 row norms (for corr)
__device__ int       g_THR[N_PTS * 2];
__device__ int       g_CNT[N_PTS];
__device__ long long g_CAND[(size_t)N_PTS * CAP];           // packed (key<<13 | 8191-col)
__device__ int       g_NBR[N_PTS * KNBR];
__device__ double    g_pb[1024];
__device__ double    g_pc[1024];

// ---------------- fast-math ----------------
__device__ __forceinline__ float f_sqrt(float x){ float r; asm("sqrt.approx.f32 %0, %1;" : "=f"(r) : "f"(x)); return r; }
__device__ __forceinline__ float f_rcp (float x){ float r; asm("rcp.approx.f32 %0, %1;"  : "=f"(r) : "f"(x)); return r; }
__device__ __forceinline__ float f_lg2 (float x){ float r; asm("lg2.approx.f32 %0, %1;"  : "=f"(r) : "f"(x)); return r; }
__device__ __forceinline__ float f_ex2 (float x){ float r; asm("ex2.approx.f32 %0, %1;"  : "=f"(r) : "f"(x)); return r; }

#define LN2F   0.69314718055994531f
#define LOG2EF 1.4426950408889634f

__device__ __forceinline__ void cp_async8(uint32_t dst, const void* src) {
    asm volatile("cp.async.ca.shared.global [%0], [%1], 8;" :: "r"(dst), "l"(src));
}

// ---------------- 1) prep: quantize + norms + counter reset ----------------
__global__ void prep_kernel(const float* __restrict__ X) {
    int warp = threadIdx.x >> 5, lane = threadIdx.x & 31;
    int row  = blockIdx.x * 8 + warp;
    const float* xr = X + (size_t)row * DIMS + lane * 4;
    float v0 = xr[0], v1 = xr[1], v2 = xr[2], v3 = xr[3];
    int q0 = __float2int_rn(fminf(fmaxf(v0 * QS, -127.f), 127.f));
    int q1 = __float2int_rn(fminf(fmaxf(v1 * QS, -127.f), 127.f));
    int q2 = __float2int_rn(fminf(fmaxf(v2 * QS, -127.f), 127.f));
    int q3 = __float2int_rn(fminf(fmaxf(v3 * QS, -127.f), 127.f));
    ((int*)g_XQ)[row * 32 + lane] =
        (q0 & 0xff) | ((q1 & 0xff) << 8) | ((q2 & 0xff) << 16) | (q3 << 24);
    float s  = v0*v0 + v1*v1 + v2*v2 + v3*v3;
    int  sq  = q0*q0 + q1*q1 + q2*q2 + q3*q3;
    #pragma unroll
    for (int off = 16; off; off >>= 1) {
        s  += __shfl_xor_sync(0xffffffffu, s,  off);
        sq += __shfl_xor_sync(0xffffffffu, sq, off);
    }
    if (lane == 0) { g_SQ[row] = s; g_SQQ[row] = sq; g_CNT[row] = 0; }
}

// ---------------- dp4a tile core for 8x8 (thresh only) ----------------
__device__ __forceinline__ void tile_dp4a_88(const char* sA, const char* sB, int tx, int ty,
                                             int acc[8][8]) {
    #pragma unroll
    for (int j = 0; j < 8; j++)
        #pragma unroll
        for (int i = 0; i < 8; i++) acc[j][i] = 0;
    const char* aBase = sA + (ty * 8) * ROWB;
    const char* bBase = sB + tx * ROWB;
    #pragma unroll 4
    for (int p = 0; p < 16; p++) {
        int2 a[8], b[8];
        #pragma unroll
        for (int j = 0; j < 8; j++) a[j] = *(const int2*)(aBase + j * ROWB + p * 8);
        #pragma unroll
        for (int i = 0; i < 8; i++) b[i] = *(const int2*)(bBase + i * 16 * ROWB + p * 8);
        #pragma unroll
        for (int j = 0; j < 8; j++)
            #pragma unroll
            for (int i = 0; i < 8; i++) {
                acc[j][i] = __dp4a(a[j].x, b[i].x, acc[j][i]);
                acc[j][i] = __dp4a(a[j].y, b[i].y, acc[j][i]);
            }
    }
}

// ======================= Phase 1: per-(row, half) threshold (1/8 subsample) =======================
#define T_SB   PANELB
#define T_SC   (2 * PANELB)
#define T_ST   (2 * PANELB + 128 * 132 * 4)
#define T_TOT  (T_ST + 256 * KNBR * 4)       // 116736

__global__ __launch_bounds__(256, 1) void thresh_kernel() {
    extern __shared__ __align__(16) char smem[];
    char* sA = smem;
    char* sB = smem + T_SB;
    int*  sSc = (int*)(smem + T_SC);
    int*  stK = (int*)(smem + T_ST);
    __shared__ int sSqqT[128];
    uint32_t sA_u = (uint32_t)__cvta_generic_to_shared(sA);
    uint32_t sB_u = (uint32_t)__cvta_generic_to_shared(sB);

    int tid = threadIdx.x;
    int rb = blockIdx.x >> 1, half = blockIdx.x & 1;
    int rowBlk = rb * 128;
    int tx = tid & 15, ty = tid >> 4;

    #pragma unroll
    for (int i = 0; i < 8; i++) {
        int c = tid + i * 256;
        int r = c >> 4, q = c & 15;
        cp_async8(sA_u + (uint32_t)(r * ROWB + q * 8), g_XQ + (size_t)(rowBlk + r) * DIMS + q * 8);
    }
    asm volatile("cp.async.commit_group;");

    int bk[KNBR];
    #pragma unroll
    for (int s = 0; s < KNBR; s++) bk[s] = (int)0x80000000;
    int srow = tid >> 1, seg = tid & 1;

    for (int t = 0; t < 4; t++) {
        #pragma unroll
        for (int i = 0; i < 8; i++) {
            int c = tid + i * 256;
            int r = c >> 4, q = c & 15;
            int j = 8 * (half * 512 + t * 128 + r);
            cp_async8(sB_u + (uint32_t)(r * ROWB + q * 8), g_XQ + (size_t)j * DIMS + q * 8);
        }
        if (tid < 128) sSqqT[tid] = g_SQQ[8 * (half * 512 + t * 128 + tid)];
        asm volatile("cp.async.commit_group;");
        asm volatile("cp.async.wait_group 0;");
        __syncthreads();

        int acc[8][8];
        tile_dp4a_88(sA, sB, tx, ty, acc);

        #pragma unroll
        for (int j = 0; j < 8; j++)
            #pragma unroll
            for (int i = 0; i < 8; i++) {
                int col = tx + 16 * i;
                sSc[(ty * 8 + j) * 132 + col] = 2 * acc[j][i] - sSqqT[col];
            }
        __syncthreads();

        const int* prow = sSc + srow * 132 + seg * 64;
        #pragma unroll 8
        for (int c = 0; c < 64; c++) {
            int v = prow[c];
            if (v > bk[KNBR - 1]) {
                int cv = v;
                #pragma unroll
                for (int s = 0; s < KNBR; s++)
                    if (cv > bk[s]) { int tf = bk[s]; bk[s] = cv; cv = tf; }
            }
        }
        __syncthreads();
    }
    #pragma unroll
    for (int s = 0; s < KNBR; s++) stK[tid * KNBR + s] = bk[s];
    __syncthreads();
    if (tid < 128) {
        const int* k0 = stK + (tid * 2) * KNBR;
        const int* k1 = stK + (tid * 2 + 1) * KNBR;
        int p0 = 0, p1 = 0, v = 0;
        #pragma unroll
        for (int s = 0; s < KNBR; s++) {
            if (k0[p0] >= k1[p1]) v = k0[p0++]; else v = k1[p1++];
        }
        g_THR[(rowBlk + tid) * 2 + half] = v;
    }
}

// ======================= Phase 2: symmetric dp4a GEMM + filter (128x64 tiles, 4x8 thread tile) ====
// grid 4160: pair = b>>1 (upper-tri I<=J), half = b&1 (64-col half of J panel)
// thread map: tx = tid&7 (cols tx+8i, i<8), ty = tid>>3 (rows ty*4+j, j<4)
__global__ __launch_bounds__(256, 3) void filter_kernel() {
    __shared__ __align__(16) char sAbuf[PANELB];     // 128 rows of I
    __shared__ __align__(16) char sBbuf[HPANELB];    // 64 rows of J-half
    __shared__ int sTI[128], sSqI[128], sTJ[64], sSqJ[64];
    uint32_t sA_u = (uint32_t)__cvta_generic_to_shared(sAbuf);
    uint32_t sB_u = (uint32_t)__cvta_generic_to_shared(sBbuf);

    int tid = threadIdx.x;
    int tx = tid & 7, ty = tid >> 3;

    int b = blockIdx.x >> 1, half = blockIdx.x & 1;
    int I = (int)floorf(64.5f - f_sqrt(64.5f * 64.5f - 2.0f * (float)b));
    while (64 * (I + 1) - ((I + 1) * I) / 2 <= b) I++;
    while (64 * I - (I * (I - 1)) / 2 > b) I--;
    int J = I + (b - (64 * I - (I * (I - 1)) / 2));
    int Ibase = I * 128, Jhalf = J * 128 + half * 64;

    #pragma unroll
    for (int i = 0; i < 8; i++) {                       // A: 2048 8B chunks
        int c = tid + i * 256;
        int r = c >> 4, q = c & 15;
        cp_async8(sA_u + (uint32_t)(r * ROWB + q * 8), g_XQ + (size_t)(Ibase + r) * DIMS + q * 8);
    }
    #pragma unroll
    for (int i = 0; i < 4; i++) {                       // B half: 1024 8B chunks
        int c = tid + i * 256;
        int r = c >> 4, q = c & 15;
        cp_async8(sB_u + (uint32_t)(r * ROWB + q * 8), g_XQ + (size_t)(Jhalf + r) * DIMS + q * 8);
    }
    asm volatile("cp.async.commit_group;");
    if (tid < 128) {
        int r = Ibase + tid;
        int t0 = g_THR[r * 2], t1 = g_THR[r * 2 + 1];
        sTI[tid] = (t0 > t1) ? t0 : t1;
        sSqI[tid] = g_SQQ[r];
    } else if (tid < 192) {
        int r = Jhalf + (tid - 128);
        int t0 = g_THR[r * 2], t1 = g_THR[r * 2 + 1];
        sTJ[tid - 128] = (t0 > t1) ? t0 : t1;
        sSqJ[tid - 128] = g_SQQ[r];
    }
    asm volatile("cp.async.wait_group 0;");
    __syncthreads();

    // ---- dp4a core: 4 rows x 8 cols per thread ----
    int acc[4][8];
    #pragma unroll
    for (int j = 0; j < 4; j++)
        #pragma unroll
        for (int i = 0; i < 8; i++) acc[j][i] = 0;
    {
        const char* aBase = sAbuf + (ty * 4) * ROWB;
        const char* bBase = sBbuf + tx * ROWB;
        #pragma unroll 4
        for (int p = 0; p < 16; p++) {
            int2 a[4], bb[8];
            #pragma unroll
            for (int j = 0; j < 4; j++) a[j] = *(const int2*)(aBase + j * ROWB + p * 8);
            #pragma unroll
            for (int i = 0; i < 8; i++) bb[i] = *(const int2*)(bBase + i * 8 * ROWB + p * 8);
            #pragma unroll
            for (int j = 0; j < 4; j++)
                #pragma unroll
                for (int i = 0; i < 8; i++) {
                    acc[j][i] = __dp4a(a[j].x, bb[i].x, acc[j][i]);
                    acc[j][i] = __dp4a(a[j].y, bb[i].y, acc[j][i]);
                }
        }
    }

    int TI[4], sqI[4], TJ[8], sqJ[8];
    #pragma unroll
    for (int j = 0; j < 4; j++) { TI[j] = sTI[ty * 4 + j]; sqI[j] = sSqI[ty * 4 + j]; }
    #pragma unroll
    for (int i = 0; i < 8; i++) { TJ[i] = sTJ[tx + 8 * i]; sqJ[i] = sSqJ[tx + 8 * i]; }

    int minSqJ = sqJ[0], minSqI = sqI[0];
    #pragma unroll
    for (int i = 1; i < 8; i++) if (sqJ[i] < minSqJ) minSqJ = sqJ[i];
    #pragma unroll
    for (int j = 1; j < 4; j++) if (sqI[j] < minSqI) minSqI = sqI[j];

    // direction I: rows of I panel, neighbors in J-half cols
    #pragma unroll
    for (int j = 0; j < 4; j++) {
        int mv = acc[j][0];
        #pragma unroll
        for (int i = 1; i < 8; i++) if (acc[j][i] > mv) mv = acc[j][i];
        if (2 * mv - minSqJ >= TI[j]) {
            int row = Ibase + ty * 4 + j;
            #pragma unroll
            for (int i = 0; i < 8; i++) {
                int key = 2 * acc[j][i] - sqJ[i];
                if (key >= TI[j]) {
                    int col = Jhalf + tx + 8 * i;
                    int pos = atomicAdd(&g_CNT[row], 1);
                    if (pos < CAP)
                        g_CAND[(size_t)row * CAP + pos] =
                            ((long long)key << 13) | (long long)(8191 - col);
                }
            }
        }
    }
    // direction J (off-diagonal only): rows of J-half, neighbors in I panel
    if (I != J) {
        #pragma unroll
        for (int i = 0; i < 8; i++) {
            int mv = acc[0][i];
            #pragma unroll
            for (int j = 1; j < 4; j++) if (acc[j][i] > mv) mv = acc[j][i];
            if (2 * mv - minSqI >= TJ[i]) {
                int row = Jhalf + tx + 8 * i;
                #pragma unroll
                for (int j = 0; j < 4; j++) {
                    int key = 2 * acc[j][i] - sqI[j];
                    if (key >= TJ[i]) {
                        int col = Ibase + ty * 4 + j;
                        int pos = atomicAdd(&g_CNT[row], 1);
                        if (pos < CAP)
                            g_CAND[(size_t)row * CAP + pos] =
                                ((long long)key << 13) | (long long)(8191 - col);
                    }
                }
            }
        }
    }
}

// ======================= Phase 3: warp-per-row top-14 =======================
__global__ void select_topk() {
    int warp = threadIdx.x >> 5, lane = threadIdx.x & 31;
    int row  = blockIdx.x * 8 + warp;
    int cnt = g_CNT[row]; if (cnt > CAP) cnt = CAP;
    const long long* cand = g_CAND + (size_t)row * CAP;
    const long long MINV = 0x8000000000000000LL;

    long long bk[KNBR];
    #pragma unroll
    for (int s = 0; s < KNBR; s++) bk[s] = MINV;
    for (int c = lane; c < cnt; c += 32) {
        long long v = cand[c];
        if (v > bk[KNBR - 1]) {
            long long cv = v;
            #pragma unroll
            for (int s = 0; s < KNBR; s++)
                if (cv > bk[s]) { long long tf = bk[s]; bk[s] = cv; cv = tf; }
        }
    }
    for (int r = 0; r < KNBR; r++) {
        long long m = bk[0];
        int owner = lane;
        #pragma unroll
        for (int off = 16; off; off >>= 1) {
            long long ov = __shfl_xor_sync(0xffffffffu, m, off);
            int       ow = __shfl_xor_sync(0xffffffffu, owner, off);
            if (ov > m) { m = ov; owner = ow; }
        }
        if (lane == owner) {
            #pragma unroll
            for (int s = 0; s < KNBR - 1; s++) bk[s] = bk[s + 1];
            bk[KNBR - 1] = MINV;
        }
        if (lane == 0) g_NBR[row * KNBR + r] = 8191 - (int)(m & 8191);
    }
}

// ---------------- bulk lo-dim loss: exact triangular grid ----------------
__global__ void bulk_kernel(const float* __restrict__ LO) {
    int b = blockIdx.x;
    int i = (int)(32.5f - f_sqrt(32.5f * 32.5f - 2.0f * (float)b));
    while ((i + 1) * 32 - ((i + 1) * i) / 2 <= b) i++;
    while (i * 32 - (i * (i - 1)) / 2 > b) i--;
    int j = i + (b - (i * 32 - (i * (i - 1)) / 2));
    int ibase = i * 256, jbase = j * 256;

    __shared__ float2 sLo[256];
    __shared__ double sred[256];
    int tid = threadIdx.x;
    const float2* lo2 = (const float2*)LO;
    int gi = ibase + tid;
    float2 me = lo2[gi];
    sLo[tid] = lo2[jbase + tid];
    __syncthreads();

    float accf = 0.f;
    if (j > i) {
        #pragma unroll 4
        for (int c = 0; c < 256; c++) {
            float2 o = sLo[c];
            float dx = me.x - o.x, dy = me.y - o.y;
            float d = f_sqrt(fmaf(dx, dx, dy * dy));
            float r = f_rcp(1.0f + d);
            accf += f_lg2((1.0f - r) + 1e-10f);
        }
        accf *= 2.0f;
    } else {
        #pragma unroll 4
        for (int c = 0; c < 256; c++) {
            int jg = jbase + c;
            float2 o = sLo[c];
            float dx = me.x - o.x, dy = me.y - o.y;
            float d = f_sqrt(fmaf(dx, dx, dy * dy));
            float r = f_rcp(1.0f + d);
            float term = f_lg2((1.0f - r) + 1e-10f);
            float w = (jg > gi) ? 2.0f : ((jg == gi) ? 1.0f : 0.0f);
            accf += w * term;
        }
    }
    sred[tid] = (double)(accf * LN2F);
    __syncthreads();
    for (int off = 128; off; off >>= 1) { if (tid < off) sred[tid] += sred[tid + off]; __syncthreads(); }
    if (tid == 0) g_pb[b] = sred[0];
}

// ---------------- exact neighbor correction ----------------
__global__ void corr_kernel(const float* __restrict__ X, const float* __restrict__ LO) {
    __shared__ double wsum[8];
    int warp = threadIdx.x >> 5, lane = threadIdx.x & 31;
    int row  = blockIdx.x * 8 + warp;
    const float* xi = X + (size_t)row * DIMS;
    float a0 = xi[lane], a1 = xi[lane + 32], a2 = xi[lane + 64], a3 = xi[lane + 96];
    const float2* lo2 = (const float2*)LO;
    float2 li = lo2[row];
    float sqi = g_SQ[row];

    float acc = 0.f;
    for (int n = 0; n < KNBR; n++) {
        int j = g_NBR[row * KNBR + n];
        const float* xj = X + (size_t)j * DIMS;
        float dot = a0 * xj[lane] + a1 * xj[lane + 32] + a2 * xj[lane + 64] + a3 * xj[lane + 96];
        #pragma unroll
        for (int off = 16; off; off >>= 1) dot += __shfl_xor_sync(0xffffffffu, dot, off);
        float d2h = fmaxf(sqi + g_SQ[j] - 2.f * dot, 0.f);
        float hd = f_sqrt(d2h);
        float hs = f_ex2(-LOG2EF * hd);
        float2 lj = lo2[j];
        float dx = li.x - lj.x, dy = li.y - lj.y;
        float ld = f_sqrt(fmaf(dx, dx, dy * dy));
        float r  = f_rcp(1.0f + ld);
        float A  = hs * (f_lg2(r + 1e-10f) * LN2F);
        float Bs = f_lg2((1.0f - r) + 1e-10f) * LN2F;
        acc += (A - Bs);
    }
    if (lane == 0) wsum[warp] = (double)acc;
    __syncthreads();
    if (threadIdx.x == 0) {
        double s = 0;
        for (int k = 0; k < 8; k++) s += wsum[k];
        g_pc[blockIdx.x] = s;
    }
}

// ---------------- deterministic final reduce ----------------
__global__ void final_kernel(float* __restrict__ out) {
    __shared__ double sred[256];
    int t = threadIdx.x;
    double s = 0;
    for (int k = t; k < 528;  k += 256) s += g_pb[k];
    for (int k = t; k < 1024; k += 256) s += g_pc[k];
    sred[t] = s;
    __syncthreads();
    for (int off = 128; off; off >>= 1) { if (t < off) sred[t] += sred[t + off]; __syncthreads(); }
    if (t == 0) out[0] = (float)(-(sred[0] / 67108864.0) * 100.0);
}

// ---------------- launch: bulk forked onto a side stream, joined before final ----------------
extern "C" void kernel_launch(void* const* d_in, const int* in_sizes, int n_in,
                              void* d_out, int out_size) {
    const float* X; const float* LO;
    if (in_sizes[0] == N_PTS * DIMS) { X = (const float*)d_in[0]; LO = (const float*)d_in[1]; }
    else                             { X = (const float*)d_in[1]; LO = (const float*)d_in[0]; }

    cudaFuncSetAttribute(thresh_kernel, cudaFuncAttributeMaxDynamicSharedMemorySize, T_TOT);

    cudaStream_t s2;
    cudaEvent_t eFork, eJoin;
    cudaStreamCreateWithFlags(&s2, cudaStreamNonBlocking);
    cudaEventCreateWithFlags(&eFork, cudaEventDisableTiming);
    cudaEventCreateWithFlags(&eJoin, cudaEventDisableTiming);

    prep_kernel  <<<N_PTS / 8, 256>>>(X);

    cudaEventRecord(eFork, 0);
    cudaStreamWaitEvent(s2, eFork, 0);
    bulk_kernel  <<<NBULK, 256, 0, s2>>>(LO);

    thresh_kernel<<<128, 256, T_TOT>>>();
    filter_kernel<<<NPAIR * 2, 256>>>();
    select_topk  <<<N_PTS / 8, 256>>>();
    corr_kernel  <<<N_PTS / 8, 256>>>(X, LO);

    cudaEventRecord(eJoin, s2);
    cudaStreamWaitEvent(0, eJoin, 0);
    final_kernel <<<1, 256>>>((float*)d_out);

    cudaEventDestroy(eFork);
    cudaEventDestroy(eJoin);
    cudaStreamDestroy(s2);
}

// round 16
// speedup vs baseline: 1.4819x; 1.0809x over previous
#include <cuda_runtime.h>
#include <cstdint>
#include <cstddef>

#define N_PTS 8192
#define DIMS  128
#define KNBR  14
#define CAP   448
#define QS    24.0f
#define ROWB  136               // smem panel row stride (bytes): conflict-free int2 LDS
#define PANELB  (128 * ROWB)    // 17408 B per 128-row int8 panel
#define HPANELB (64 * ROWB)     // 8704 B per 64-row half panel
#define NPAIR 2080
#define NBULK 528

// ---------------- scratch ----------------
__device__ __align__(16) signed char g_XQ[N_PTS * DIMS];   // 1 MB int8, L2-resident
__device__ int       g_SQQ[N_PTS];                          // |q_i|^2 exact int
__device__ float     g_SQ[N_PTS];                           // fp32 row norms (for corr)
__device__ int       g_THR[N_PTS * 2];
__device__ int       g_CNT[N_PTS];
__device__ long long g_CAND[(size_t)N_PTS * CAP];           // packed (key<<13 | 8191-col)
__device__ int       g_NBR[N_PTS * KNBR];
__device__ double    g_pb[1024];
__device__ double    g_pc[1024];

// ---------------- fast-math ----------------
__device__ __forceinline__ float f_sqrt(float x){ float r; asm("sqrt.approx.f32 %0, %1;" : "=f"(r) : "f"(x)); return r; }
__device__ __forceinline__ float f_rcp (float x){ float r; asm("rcp.approx.f32 %0, %1;"  : "=f"(r) : "f"(x)); return r; }
__device__ __forceinline__ float f_lg2 (float x){ float r; asm("lg2.approx.f32 %0, %1;"  : "=f"(r) : "f"(x)); return r; }
__device__ __forceinline__ float f_ex2 (float x){ float r; asm("ex2.approx.f32 %0, %1;"  : "=f"(r) : "f"(x)); return r; }

#define LN2F   0.69314718055994531f
#define LOG2EF 1.4426950408889634f

__device__ __forceinline__ void cp_async8(uint32_t dst, const void* src) {
    asm volatile("cp.async.ca.shared.global [%0], [%1], 8;" :: "r"(dst), "l"(src));
}

// ---------------- 1) prep: quantize + norms + counter reset ----------------
__global__ void prep_kernel(const float* __restrict__ X) {
    int warp = threadIdx.x >> 5, lane = threadIdx.x & 31;
    int row  = blockIdx.x * 8 + warp;
    const float* xr = X + (size_t)row * DIMS + lane * 4;
    float v0 = xr[0], v1 = xr[1], v2 = xr[2], v3 = xr[3];
    int q0 = __float2int_rn(fminf(fmaxf(v0 * QS, -127.f), 127.f));
    int q1 = __float2int_rn(fminf(fmaxf(v1 * QS, -127.f), 127.f));
    int q2 = __float2int_rn(fminf(fmaxf(v2 * QS, -127.f), 127.f));
    int q3 = __float2int_rn(fminf(fmaxf(v3 * QS, -127.f), 127.f));
    ((int*)g_XQ)[row * 32 + lane] =
        (q0 & 0xff) | ((q1 & 0xff) << 8) | ((q2 & 0xff) << 16) | (q3 << 24);
    float s  = v0*v0 + v1*v1 + v2*v2 + v3*v3;
    int  sq  = q0*q0 + q1*q1 + q2*q2 + q3*q3;
    #pragma unroll
    for (int off = 16; off; off >>= 1) {
        s  += __shfl_xor_sync(0xffffffffu, s,  off);
        sq += __shfl_xor_sync(0xffffffffu, sq, off);
    }
    if (lane == 0) { g_SQ[row] = s; g_SQQ[row] = sq; g_CNT[row] = 0; }
}

// ---------------- dp4a tile core for 8x8 (thresh only) ----------------
__device__ __forceinline__ void tile_dp4a_88(const char* sA, const char* sB, int tx, int ty,
                                             int acc[8][8]) {
    #pragma unroll
    for (int j = 0; j < 8; j++)
        #pragma unroll
        for (int i = 0; i < 8; i++) acc[j][i] = 0;
    const char* aBase = sA + (ty * 8) * ROWB;
    const char* bBase = sB + tx * ROWB;
    #pragma unroll 4
    for (int p = 0; p < 16; p++) {
        int2 a[8], b[8];
        #pragma unroll
        for (int j = 0; j < 8; j++) a[j] = *(const int2*)(aBase + j * ROWB + p * 8);
        #pragma unroll
        for (int i = 0; i < 8; i++) b[i] = *(const int2*)(bBase + i * 16 * ROWB + p * 8);
        #pragma unroll
        for (int j = 0; j < 8; j++)
            #pragma unroll
            for (int i = 0; i < 8; i++) {
                acc[j][i] = __dp4a(a[j].x, b[i].x, acc[j][i]);
                acc[j][i] = __dp4a(a[j].y, b[i].y, acc[j][i]);
            }
    }
}

// ======================= Phase 1: per-(row, half) threshold (1/8 subsample) =======================
#define T_SB   PANELB
#define T_SC   (2 * PANELB)
#define T_ST   (2 * PANELB + 128 * 132 * 4)
#define T_TOT  (T_ST + 256 * KNBR * 4)       // 116736

__global__ __launch_bounds__(256, 1) void thresh_kernel() {
    extern __shared__ __align__(16) char smem[];
    char* sA = smem;
    char* sB = smem + T_SB;
    int*  sSc = (int*)(smem + T_SC);
    int*  stK = (int*)(smem + T_ST);
    __shared__ int sSqqT[128];
    uint32_t sA_u = (uint32_t)__cvta_generic_to_shared(sA);
    uint32_t sB_u = (uint32_t)__cvta_generic_to_shared(sB);

    int tid = threadIdx.x;
    int rb = blockIdx.x >> 1, half = blockIdx.x & 1;
    int rowBlk = rb * 128;
    int tx = tid & 15, ty = tid >> 4;

    #pragma unroll
    for (int i = 0; i < 8; i++) {
        int c = tid + i * 256;
        int r = c >> 4, q = c & 15;
        cp_async8(sA_u + (uint32_t)(r * ROWB + q * 8), g_XQ + (size_t)(rowBlk + r) * DIMS + q * 8);
    }
    asm volatile("cp.async.commit_group;");

    int bk[KNBR];
    #pragma unroll
    for (int s = 0; s < KNBR; s++) bk[s] = (int)0x80000000;
    int srow = tid >> 1, seg = tid & 1;

    for (int t = 0; t < 4; t++) {
        #pragma unroll
        for (int i = 0; i < 8; i++) {
            int c = tid + i * 256;
            int r = c >> 4, q = c & 15;
            int j = 8 * (half * 512 + t * 128 + r);
            cp_async8(sB_u + (uint32_t)(r * ROWB + q * 8), g_XQ + (size_t)j * DIMS + q * 8);
        }
        if (tid < 128) sSqqT[tid] = g_SQQ[8 * (half * 512 + t * 128 + tid)];
        asm volatile("cp.async.commit_group;");
        asm volatile("cp.async.wait_group 0;");
        __syncthreads();

        int acc[8][8];
        tile_dp4a_88(sA, sB, tx, ty, acc);

        #pragma unroll
        for (int j = 0; j < 8; j++)
            #pragma unroll
            for (int i = 0; i < 8; i++) {
                int col = tx + 16 * i;
                sSc[(ty * 8 + j) * 132 + col] = 2 * acc[j][i] - sSqqT[col];
            }
        __syncthreads();

        const int* prow = sSc + srow * 132 + seg * 64;
        #pragma unroll 8
        for (int c = 0; c < 64; c++) {
            int v = prow[c];
            if (v > bk[KNBR - 1]) {
                int cv = v;
                #pragma unroll
                for (int s = 0; s < KNBR; s++)
                    if (cv > bk[s]) { int tf = bk[s]; bk[s] = cv; cv = tf; }
            }
        }
        __syncthreads();
    }
    #pragma unroll
    for (int s = 0; s < KNBR; s++) stK[tid * KNBR + s] = bk[s];
    __syncthreads();
    if (tid < 128) {
        const int* k0 = stK + (tid * 2) * KNBR;
        const int* k1 = stK + (tid * 2 + 1) * KNBR;
        int p0 = 0, p1 = 0, v = 0;
        #pragma unroll
        for (int s = 0; s < KNBR; s++) {
            if (k0[p0] >= k1[p1]) v = k0[p0++]; else v = k1[p1++];
        }
        g_THR[(rowBlk + tid) * 2 + half] = v;
    }
}

// ======================= Phase 2: symmetric dp4a GEMM + filter (128x64 tiles, 4x8 thread tile) ====
// grid 4160: pair = b>>1 (upper-tri I<=J), half = b&1 (64-col half of J panel)
// 4 blocks/SM target: b-operands split into two halves of 4 to keep live regs <= 64
__global__ __launch_bounds__(256, 4) void filter_kernel() {
    __shared__ __align__(16) char sAbuf[PANELB];     // 128 rows of I
    __shared__ __align__(16) char sBbuf[HPANELB];    // 64 rows of J-half
    __shared__ int sTI[128], sSqI[128], sTJ[64], sSqJ[64];
    uint32_t sA_u = (uint32_t)__cvta_generic_to_shared(sAbuf);
    uint32_t sB_u = (uint32_t)__cvta_generic_to_shared(sBbuf);

    int tid = threadIdx.x;
    int tx = tid & 7, ty = tid >> 3;

    int b = blockIdx.x >> 1, half = blockIdx.x & 1;
    int I = (int)floorf(64.5f - f_sqrt(64.5f * 64.5f - 2.0f * (float)b));
    while (64 * (I + 1) - ((I + 1) * I) / 2 <= b) I++;
    while (64 * I - (I * (I - 1)) / 2 > b) I--;
    int J = I + (b - (64 * I - (I * (I - 1)) / 2));
    int Ibase = I * 128, Jhalf = J * 128 + half * 64;

    #pragma unroll
    for (int i = 0; i < 8; i++) {                       // A: 2048 8B chunks
        int c = tid + i * 256;
        int r = c >> 4, q = c & 15;
        cp_async8(sA_u + (uint32_t)(r * ROWB + q * 8), g_XQ + (size_t)(Ibase + r) * DIMS + q * 8);
    }
    #pragma unroll
    for (int i = 0; i < 4; i++) {                       // B half: 1024 8B chunks
        int c = tid + i * 256;
        int r = c >> 4, q = c & 15;
        cp_async8(sB_u + (uint32_t)(r * ROWB + q * 8), g_XQ + (size_t)(Jhalf + r) * DIMS + q * 8);
    }
    asm volatile("cp.async.commit_group;");
    if (tid < 128) {
        int r = Ibase + tid;
        int t0 = g_THR[r * 2], t1 = g_THR[r * 2 + 1];
        sTI[tid] = (t0 > t1) ? t0 : t1;
        sSqI[tid] = g_SQQ[r];
    } else if (tid < 192) {
        int r = Jhalf + (tid - 128);
        int t0 = g_THR[r * 2], t1 = g_THR[r * 2 + 1];
        sTJ[tid - 128] = (t0 > t1) ? t0 : t1;
        sSqJ[tid - 128] = g_SQQ[r];
    }
    asm volatile("cp.async.wait_group 0;");
    __syncthreads();

    // ---- dp4a core: 4 rows x 8 cols per thread, b in two 4-col halves ----
    int acc[4][8];
    #pragma unroll
    for (int j = 0; j < 4; j++)
        #pragma unroll
        for (int i = 0; i < 8; i++) acc[j][i] = 0;
    {
        const char* aBase = sAbuf + (ty * 4) * ROWB;
        const char* bBase = sBbuf + tx * ROWB;
        #pragma unroll 4
        for (int p = 0; p < 16; p++) {
            int2 a[4];
            #pragma unroll
            for (int j = 0; j < 4; j++) a[j] = *(const int2*)(aBase + j * ROWB + p * 8);
            #pragma unroll
            for (int h = 0; h < 2; h++) {
                int2 bb[4];
                #pragma unroll
                for (int i = 0; i < 4; i++)
                    bb[i] = *(const int2*)(bBase + (h * 4 + i) * 8 * ROWB + p * 8);
                #pragma unroll
                for (int j = 0; j < 4; j++)
                    #pragma unroll
                    for (int i = 0; i < 4; i++) {
                        acc[j][h * 4 + i] = __dp4a(a[j].x, bb[i].x, acc[j][h * 4 + i]);
                        acc[j][h * 4 + i] = __dp4a(a[j].y, bb[i].y, acc[j][h * 4 + i]);
                    }
            }
        }
    }

    int TI[4], sqI[4], TJ[8], sqJ[8];
    #pragma unroll
    for (int j = 0; j < 4; j++) { TI[j] = sTI[ty * 4 + j]; sqI[j] = sSqI[ty * 4 + j]; }
    #pragma unroll
    for (int i = 0; i < 8; i++) { TJ[i] = sTJ[tx + 8 * i]; sqJ[i] = sSqJ[tx + 8 * i]; }

    int minSqJ = sqJ[0], minSqI = sqI[0];
    #pragma unroll
    for (int i = 1; i < 8; i++) if (sqJ[i] < minSqJ) minSqJ = sqJ[i];
    #pragma unroll
    for (int j = 1; j < 4; j++) if (sqI[j] < minSqI) minSqI = sqI[j];

    // direction I: rows of I panel, neighbors in J-half cols
    #pragma unroll
    for (int j = 0; j < 4; j++) {
        int mv = acc[j][0];
        #pragma unroll
        for (int i = 1; i < 8; i++) if (acc[j][i] > mv) mv = acc[j][i];
        if (2 * mv - minSqJ >= TI[j]) {
            int row = Ibase + ty * 4 + j;
            #pragma unroll
            for (int i = 0; i < 8; i++) {
                int key = 2 * acc[j][i] - sqJ[i];
                if (key >= TI[j]) {
                    int col = Jhalf + tx + 8 * i;
                    int pos = atomicAdd(&g_CNT[row], 1);
                    if (pos < CAP)
                        g_CAND[(size_t)row * CAP + pos] =
                            ((long long)key << 13) | (long long)(8191 - col);
                }
            }
        }
    }
    // direction J (off-diagonal only): rows of J-half, neighbors in I panel
    if (I != J) {
        #pragma unroll
        for (int i = 0; i < 8; i++) {
            int mv = acc[0][i];
            #pragma unroll
            for (int j = 1; j < 4; j++) if (acc[j][i] > mv) mv = acc[j][i];
            if (2 * mv - minSqI >= TJ[i]) {
                int row = Jhalf + tx + 8 * i;
                #pragma unroll
                for (int j = 0; j < 4; j++) {
                    int key = 2 * acc[j][i] - sqI[j];
                    if (key >= TJ[i]) {
                        int col = Ibase + ty * 4 + j;
                        int pos = atomicAdd(&g_CNT[row], 1);
                        if (pos < CAP)
                            g_CAND[(size_t)row * CAP + pos] =
                                ((long long)key << 13) | (long long)(8191 - col);
                    }
                }
            }
        }
    }
}

// ======================= Phase 3: warp-per-row top-14 =======================
__global__ void select_topk() {
    int warp = threadIdx.x >> 5, lane = threadIdx.x & 31;
    int row  = blockIdx.x * 8 + warp;
    int cnt = g_CNT[row]; if (cnt > CAP) cnt = CAP;
    const long long* cand = g_CAND + (size_t)row * CAP;
    const long long MINV = 0x8000000000000000LL;

    long long bk[KNBR];
    #pragma unroll
    for (int s = 0; s < KNBR; s++) bk[s] = MINV;
    for (int c = lane; c < cnt; c += 32) {
        long long v = cand[c];
        if (v > bk[KNBR - 1]) {
            long long cv = v;
            #pragma unroll
            for (int s = 0; s < KNBR; s++)
                if (cv > bk[s]) { long long tf = bk[s]; bk[s] = cv; cv = tf; }
        }
    }
    for (int r = 0; r < KNBR; r++) {
        long long m = bk[0];
        int owner = lane;
        #pragma unroll
        for (int off = 16; off; off >>= 1) {
            long long ov = __shfl_xor_sync(0xffffffffu, m, off);
            int       ow = __shfl_xor_sync(0xffffffffu, owner, off);
            if (ov > m) { m = ov; owner = ow; }
        }
        if (lane == owner) {
            #pragma unroll
            for (int s = 0; s < KNBR - 1; s++) bk[s] = bk[s + 1];
            bk[KNBR - 1] = MINV;
        }
        if (lane == 0) g_NBR[row * KNBR + r] = 8191 - (int)(m & 8191);
    }
}

// ---------------- bulk lo-dim loss: exact triangular grid ----------------
__global__ void bulk_kernel(const float* __restrict__ LO) {
    int b = blockIdx.x;
    int i = (int)(32.5f - f_sqrt(32.5f * 32.5f - 2.0f * (float)b));
    while ((i + 1) * 32 - ((i + 1) * i) / 2 <= b) i++;
    while (i * 32 - (i * (i - 1)) / 2 > b) i--;
    int j = i + (b - (i * 32 - (i * (i - 1)) / 2));
    int ibase = i * 256, jbase = j * 256;

    __shared__ float2 sLo[256];
    __shared__ double sred[256];
    int tid = threadIdx.x;
    const float2* lo2 = (const float2*)LO;
    int gi = ibase + tid;
    float2 me = lo2[gi];
    sLo[tid] = lo2[jbase + tid];
    __syncthreads();

    float accf = 0.f;
    if (j > i) {
        #pragma unroll 4
        for (int c = 0; c < 256; c++) {
            float2 o = sLo[c];
            float dx = me.x - o.x, dy = me.y - o.y;
            float d = f_sqrt(fmaf(dx, dx, dy * dy));
            float r = f_rcp(1.0f + d);
            accf += f_lg2((1.0f - r) + 1e-10f);
        }
        accf *= 2.0f;
    } else {
        #pragma unroll 4
        for (int c = 0; c < 256; c++) {
            int jg = jbase + c;
            float2 o = sLo[c];
            float dx = me.x - o.x, dy = me.y - o.y;
            float d = f_sqrt(fmaf(dx, dx, dy * dy));
            float r = f_rcp(1.0f + d);
            float term = f_lg2((1.0f - r) + 1e-10f);
            float w = (jg > gi) ? 2.0f : ((jg == gi) ? 1.0f : 0.0f);
            accf += w * term;
        }
    }
    sred[tid] = (double)(accf * LN2F);
    __syncthreads();
    for (int off = 128; off; off >>= 1) { if (tid < off) sred[tid] += sred[tid + off]; __syncthreads(); }
    if (tid == 0) g_pb[b] = sred[0];
}

// ---------------- exact neighbor correction ----------------
__global__ void corr_kernel(const float* __restrict__ X, const float* __restrict__ LO) {
    __shared__ double wsum[8];
    int warp = threadIdx.x >> 5, lane = threadIdx.x & 31;
    int row  = blockIdx.x * 8 + warp;
    const float* xi = X + (size_t)row * DIMS;
    float a0 = xi[lane], a1 = xi[lane + 32], a2 = xi[lane + 64], a3 = xi[lane + 96];
    const float2* lo2 = (const float2*)LO;
    float2 li = lo2[row];
    float sqi = g_SQ[row];

    float acc = 0.f;
    for (int n = 0; n < KNBR; n++) {
        int j = g_NBR[row * KNBR + n];
        const float* xj = X + (size_t)j * DIMS;
        float dot = a0 * xj[lane] + a1 * xj[lane + 32] + a2 * xj[lane + 64] + a3 * xj[lane + 96];
        #pragma unroll
        for (int off = 16; off; off >>= 1) dot += __shfl_xor_sync(0xffffffffu, dot, off);
        float d2h = fmaxf(sqi + g_SQ[j] - 2.f * dot, 0.f);
        float hd = f_sqrt(d2h);
        float hs = f_ex2(-LOG2EF * hd);
        float2 lj = lo2[j];
        float dx = li.x - lj.x, dy = li.y - lj.y;
        float ld = f_sqrt(fmaf(dx, dx, dy * dy));
        float r  = f_rcp(1.0f + ld);
        float A  = hs * (f_lg2(r + 1e-10f) * LN2F);
        float Bs = f_lg2((1.0f - r) + 1e-10f) * LN2F;
        acc += (A - Bs);
    }
    if (lane == 0) wsum[warp] = (double)acc;
    __syncthreads();
    if (threadIdx.x == 0) {
        double s = 0;
        for (int k = 0; k < 8; k++) s += wsum[k];
        g_pc[blockIdx.x] = s;
    }
}

// ---------------- deterministic final reduce ----------------
__global__ void final_kernel(float* __restrict__ out) {
    __shared__ double sred[256];
    int t = threadIdx.x;
    double s = 0;
    for (int k = t; k < 528;  k += 256) s += g_pb[k];
    for (int k = t; k < 1024; k += 256) s += g_pc[k];
    sred[t] = s;
    __syncthreads();
    for (int off = 128; off; off >>= 1) { if (t < off) sred[t] += sred[t + off]; __syncthreads(); }
    if (t == 0) out[0] = (float)(-(sred[0] / 67108864.0) * 100.0);
}

// ---------------- launch: bulk forked onto a side stream, joined before final ----------------
extern "C" void kernel_launch(void* const* d_in, const int* in_sizes, int n_in,
                              void* d_out, int out_size) {
    const float* X; const float* LO;
    if (in_sizes[0] == N_PTS * DIMS) { X = (const float*)d_in[0]; LO = (const float*)d_in[1]; }
    else                             { X = (const float*)d_in[1]; LO = (const float*)d_in[0]; }

    cudaFuncSetAttribute(thresh_kernel, cudaFuncAttributeMaxDynamicSharedMemorySize, T_TOT);

    cudaStream_t s2;
    cudaEvent_t eFork, eJoin;
    cudaStreamCreateWithFlags(&s2, cudaStreamNonBlocking);
    cudaEventCreateWithFlags(&eFork, cudaEventDisableTiming);
    cudaEventCreateWithFlags(&eJoin, cudaEventDisableTiming);

    prep_kernel  <<<N_PTS / 8, 256>>>(X);

    cudaEventRecord(eFork, 0);
    cudaStreamWaitEvent(s2, eFork, 0);
    bulk_kernel  <<<NBULK, 256, 0, s2>>>(LO);

    thresh_kernel<<<128, 256, T_TOT>>>();
    filter_kernel<<<NPAIR * 2, 256>>>();
    select_topk  <<<N_PTS / 8, 256>>>();
    corr_kernel  <<<N_PTS / 8, 256>>>(X, LO);

    cudaEventRecord(eJoin, s2);
    cudaStreamWaitEvent(0, eJoin, 0);
    final_kernel <<<1, 256>>>((float*)d_out);

    cudaEventDestroy(eFork);
    cudaEventDestroy(eJoin);
    cudaStreamDestroy(s2);
}

// round 17
// speedup vs baseline: 1.5666x; 1.0572x over previous
#include <cuda_runtime.h>
#include <cstdint>
#include <cstddef>

#define N_PTS 8192
#define DIMS  128
#define KNBR  14
#define CAP   448
#define QS    24.0f
#define ROWB  136               // smem panel row stride (bytes): conflict-free int2 LDS
#define PANELB  (128 * ROWB)    // 17408 B per 128-row int8 panel
#define QPANELB (64 * ROWB)     // 8704 B per 64-row panel
#define NPAIR 2080
#define NBULK 528

// ---------------- scratch ----------------
__device__ __align__(16) signed char g_XQ[N_PTS * DIMS];   // 1 MB int8, L2-resident
__device__ int       g_SQQ[N_PTS];                          // |q_i|^2 exact int
__device__ float     g_SQ[N_PTS];                           // fp32 row norms (for corr)
__device__ int       g_THR[N_PTS * 2];
__device__ int       g_CNT[N_PTS];
__device__ long long g_CAND[(size_t)N_PTS * CAP];           // packed (key<<13 | 8191-col)
__device__ int       g_NBR[N_PTS * KNBR];
__device__ double    g_pb[1024];
__device__ double    g_pc[1024];

// ---------------- fast-math ----------------
__device__ __forceinline__ float f_sqrt(float x){ float r; asm("sqrt.approx.f32 %0, %1;" : "=f"(r) : "f"(x)); return r; }
__device__ __forceinline__ float f_rcp (float x){ float r; asm("rcp.approx.f32 %0, %1;"  : "=f"(r) : "f"(x)); return r; }
__device__ __forceinline__ float f_lg2 (float x){ float r; asm("lg2.approx.f32 %0, %1;"  : "=f"(r) : "f"(x)); return r; }
__device__ __forceinline__ float f_ex2 (float x){ float r; asm("ex2.approx.f32 %0, %1;"  : "=f"(r) : "f"(x)); return r; }

#define LN2F   0.69314718055994531f
#define LOG2EF 1.4426950408889634f

__device__ __forceinline__ void cp_async8(uint32_t dst, const void* src) {
    asm volatile("cp.async.ca.shared.global [%0], [%1], 8;" :: "r"(dst), "l"(src));
}

// ---------------- 1) prep: quantize + norms + counter reset ----------------
__global__ void prep_kernel(const float* __restrict__ X) {
    int warp = threadIdx.x >> 5, lane = threadIdx.x & 31;
    int row  = blockIdx.x * 8 + warp;
    const float* xr = X + (size_t)row * DIMS + lane * 4;
    float v0 = xr[0], v1 = xr[1], v2 = xr[2], v3 = xr[3];
    int q0 = __float2int_rn(fminf(fmaxf(v0 * QS, -127.f), 127.f));
    int q1 = __float2int_rn(fminf(fmaxf(v1 * QS, -127.f), 127.f));
    int q2 = __float2int_rn(fminf(fmaxf(v2 * QS, -127.f), 127.f));
    int q3 = __float2int_rn(fminf(fmaxf(v3 * QS, -127.f), 127.f));
    ((int*)g_XQ)[row * 32 + lane] =
        (q0 & 0xff) | ((q1 & 0xff) << 8) | ((q2 & 0xff) << 16) | (q3 << 24);
    float s  = v0*v0 + v1*v1 + v2*v2 + v3*v3;
    int  sq  = q0*q0 + q1*q1 + q2*q2 + q3*q3;
    #pragma unroll
    for (int off = 16; off; off >>= 1) {
        s  += __shfl_xor_sync(0xffffffffu, s,  off);
        sq += __shfl_xor_sync(0xffffffffu, sq, off);
    }
    if (lane == 0) { g_SQ[row] = s; g_SQQ[row] = sq; g_CNT[row] = 0; }
}

// ---------------- dp4a tile core for 8x8 (thresh only) ----------------
__device__ __forceinline__ void tile_dp4a_88(const char* sA, const char* sB, int tx, int ty,
                                             int acc[8][8]) {
    #pragma unroll
    for (int j = 0; j < 8; j++)
        #pragma unroll
        for (int i = 0; i < 8; i++) acc[j][i] = 0;
    const char* aBase = sA + (ty * 8) * ROWB;
    const char* bBase = sB + tx * ROWB;
    #pragma unroll 4
    for (int p = 0; p < 16; p++) {
        int2 a[8], b[8];
        #pragma unroll
        for (int j = 0; j < 8; j++) a[j] = *(const int2*)(aBase + j * ROWB + p * 8);
        #pragma unroll
        for (int i = 0; i < 8; i++) b[i] = *(const int2*)(bBase + i * 16 * ROWB + p * 8);
        #pragma unroll
        for (int j = 0; j < 8; j++)
            #pragma unroll
            for (int i = 0; i < 8; i++) {
                acc[j][i] = __dp4a(a[j].x, b[i].x, acc[j][i]);
                acc[j][i] = __dp4a(a[j].y, b[i].y, acc[j][i]);
            }
    }
}

// ======================= Phase 1: per-(row, half) threshold (1/8 subsample) =======================
#define T_SB   PANELB
#define T_SC   (2 * PANELB)
#define T_ST   (2 * PANELB + 128 * 132 * 4)
#define T_TOT  (T_ST + 256 * KNBR * 4)       // 116736

__global__ __launch_bounds__(256, 1) void thresh_kernel() {
    extern __shared__ __align__(16) char smem[];
    char* sA = smem;
    char* sB = smem + T_SB;
    int*  sSc = (int*)(smem + T_SC);
    int*  stK = (int*)(smem + T_ST);
    __shared__ int sSqqT[128];
    uint32_t sA_u = (uint32_t)__cvta_generic_to_shared(sA);
    uint32_t sB_u = (uint32_t)__cvta_generic_to_shared(sB);

    int tid = threadIdx.x;
    int rb = blockIdx.x >> 1, half = blockIdx.x & 1;
    int rowBlk = rb * 128;
    int tx = tid & 15, ty = tid >> 4;

    #pragma unroll
    for (int i = 0; i < 8; i++) {
        int c = tid + i * 256;
        int r = c >> 4, q = c & 15;
        cp_async8(sA_u + (uint32_t)(r * ROWB + q * 8), g_XQ + (size_t)(rowBlk + r) * DIMS + q * 8);
    }
    asm volatile("cp.async.commit_group;");

    int bk[KNBR];
    #pragma unroll
    for (int s = 0; s < KNBR; s++) bk[s] = (int)0x80000000;
    int srow = tid >> 1, seg = tid & 1;

    for (int t = 0; t < 4; t++) {
        #pragma unroll
        for (int i = 0; i < 8; i++) {
            int c = tid + i * 256;
            int r = c >> 4, q = c & 15;
            int j = 8 * (half * 512 + t * 128 + r);
            cp_async8(sB_u + (uint32_t)(r * ROWB + q * 8), g_XQ + (size_t)j * DIMS + q * 8);
        }
        if (tid < 128) sSqqT[tid] = g_SQQ[8 * (half * 512 + t * 128 + tid)];
        asm volatile("cp.async.commit_group;");
        asm volatile("cp.async.wait_group 0;");
        __syncthreads();

        int acc[8][8];
        tile_dp4a_88(sA, sB, tx, ty, acc);

        #pragma unroll
        for (int j = 0; j < 8; j++)
            #pragma unroll
            for (int i = 0; i < 8; i++) {
                int col = tx + 16 * i;
                sSc[(ty * 8 + j) * 132 + col] = 2 * acc[j][i] - sSqqT[col];
            }
        __syncthreads();

        const int* prow = sSc + srow * 132 + seg * 64;
        #pragma unroll 8
        for (int c = 0; c < 64; c++) {
            int v = prow[c];
            if (v > bk[KNBR - 1]) {
                int cv = v;
                #pragma unroll
                for (int s = 0; s < KNBR; s++)
                    if (cv > bk[s]) { int tf = bk[s]; bk[s] = cv; cv = tf; }
            }
        }
        __syncthreads();
    }
    #pragma unroll
    for (int s = 0; s < KNBR; s++) stK[tid * KNBR + s] = bk[s];
    __syncthreads();
    if (tid < 128) {
        const int* k0 = stK + (tid * 2) * KNBR;
        const int* k1 = stK + (tid * 2 + 1) * KNBR;
        int p0 = 0, p1 = 0, v = 0;
        #pragma unroll
        for (int s = 0; s < KNBR; s++) {
            if (k0[p0] >= k1[p1]) v = k0[p0++]; else v = k1[p1++];
        }
        g_THR[(rowBlk + tid) * 2 + half] = v;
    }
}

// ======================= Phase 2: symmetric dp4a GEMM + filter (64x64 tiles, 4x4 thread tile) ====
// grid 8320: pair = b>>2 (upper-tri I<=J), sub = b&3 -> si=sub>>1 (I 64-row half), sj=sub&1 (J 64-col half)
// thread map: tx = tid&15 (cols tx+16i, i<4), ty = tid>>4 (rows ty*4+j, j<4)
__global__ __launch_bounds__(256, 5) void filter_kernel() {
    __shared__ __align__(16) char sAbuf[QPANELB];    // 64 rows of I-half
    __shared__ __align__(16) char sBbuf[QPANELB];    // 64 rows of J-half
    __shared__ int sTI[64], sSqI[64], sTJ[64], sSqJ[64];
    uint32_t sA_u = (uint32_t)__cvta_generic_to_shared(sAbuf);
    uint32_t sB_u = (uint32_t)__cvta_generic_to_shared(sBbuf);

    int tid = threadIdx.x;
    int tx = tid & 15, ty = tid >> 4;

    int b = blockIdx.x >> 2, sub = blockIdx.x & 3;
    int si = sub >> 1, sj = sub & 1;
    int I = (int)floorf(64.5f - f_sqrt(64.5f * 64.5f - 2.0f * (float)b));
    while (64 * (I + 1) - ((I + 1) * I) / 2 <= b) I++;
    while (64 * I - (I * (I - 1)) / 2 > b) I--;
    int J = I + (b - (64 * I - (I * (I - 1)) / 2));
    int Ihalf = I * 128 + si * 64, Jhalf = J * 128 + sj * 64;

    #pragma unroll
    for (int i = 0; i < 4; i++) {                       // A: 1024 8B chunks
        int c = tid + i * 256;
        int r = c >> 4, q = c & 15;
        cp_async8(sA_u + (uint32_t)(r * ROWB + q * 8), g_XQ + (size_t)(Ihalf + r) * DIMS + q * 8);
    }
    #pragma unroll
    for (int i = 0; i < 4; i++) {                       // B: 1024 8B chunks
        int c = tid + i * 256;
        int r = c >> 4, q = c & 15;
        cp_async8(sB_u + (uint32_t)(r * ROWB + q * 8), g_XQ + (size_t)(Jhalf + r) * DIMS + q * 8);
    }
    asm volatile("cp.async.commit_group;");
    if (tid < 64) {
        int r = Ihalf + tid;
        int t0 = g_THR[r * 2], t1 = g_THR[r * 2 + 1];
        sTI[tid] = (t0 > t1) ? t0 : t1;
        sSqI[tid] = g_SQQ[r];
    } else if (tid < 128) {
        int r = Jhalf + (tid - 64);
        int t0 = g_THR[r * 2], t1 = g_THR[r * 2 + 1];
        sTJ[tid - 64] = (t0 > t1) ? t0 : t1;
        sSqJ[tid - 64] = g_SQQ[r];
    }
    asm volatile("cp.async.wait_group 0;");
    __syncthreads();

    // ---- dp4a core: 4 rows x 4 cols per thread ----
    int acc[4][4];
    #pragma unroll
    for (int j = 0; j < 4; j++)
        #pragma unroll
        for (int i = 0; i < 4; i++) acc[j][i] = 0;
    {
        const char* aBase = sAbuf + (ty * 4) * ROWB;
        const char* bBase = sBbuf + tx * ROWB;
        #pragma unroll 4
        for (int p = 0; p < 16; p++) {
            int2 a[4], bb[4];
            #pragma unroll
            for (int j = 0; j < 4; j++) a[j] = *(const int2*)(aBase + j * ROWB + p * 8);
            #pragma unroll
            for (int i = 0; i < 4; i++) bb[i] = *(const int2*)(bBase + i * 16 * ROWB + p * 8);
            #pragma unroll
            for (int j = 0; j < 4; j++)
                #pragma unroll
                for (int i = 0; i < 4; i++) {
                    acc[j][i] = __dp4a(a[j].x, bb[i].x, acc[j][i]);
                    acc[j][i] = __dp4a(a[j].y, bb[i].y, acc[j][i]);
                }
        }
    }

    int TI[4], sqI[4], TJ[4], sqJ[4];
    #pragma unroll
    for (int j = 0; j < 4; j++) { TI[j] = sTI[ty * 4 + j]; sqI[j] = sSqI[ty * 4 + j]; }
    #pragma unroll
    for (int i = 0; i < 4; i++) { TJ[i] = sTJ[tx + 16 * i]; sqJ[i] = sSqJ[tx + 16 * i]; }

    int minSqJ = sqJ[0], minSqI = sqI[0];
    #pragma unroll
    for (int i = 1; i < 4; i++) if (sqJ[i] < minSqJ) minSqJ = sqJ[i];
    #pragma unroll
    for (int j = 1; j < 4; j++) if (sqI[j] < minSqI) minSqI = sqI[j];

    // direction I: rows of I-half, neighbors in J-half cols
    #pragma unroll
    for (int j = 0; j < 4; j++) {
        int mv = acc[j][0];
        #pragma unroll
        for (int i = 1; i < 4; i++) if (acc[j][i] > mv) mv = acc[j][i];
        if (2 * mv - minSqJ >= TI[j]) {
            int row = Ihalf + ty * 4 + j;
            #pragma unroll
            for (int i = 0; i < 4; i++) {
                int key = 2 * acc[j][i] - sqJ[i];
                if (key >= TI[j]) {
                    int col = Jhalf + tx + 16 * i;
                    int pos = atomicAdd(&g_CNT[row], 1);
                    if (pos < CAP)
                        g_CAND[(size_t)row * CAP + pos] =
                            ((long long)key << 13) | (long long)(8191 - col);
                }
            }
        }
    }
    // direction J (off-diagonal panel pairs only)
    if (I != J) {
        #pragma unroll
        for (int i = 0; i < 4; i++) {
            int mv = acc[0][i];
            #pragma unroll
            for (int j = 1; j < 4; j++) if (acc[j][i] > mv) mv = acc[j][i];
            if (2 * mv - minSqI >= TJ[i]) {
                int row = Jhalf + tx + 16 * i;
                #pragma unroll
                for (int j = 0; j < 4; j++) {
                    int key = 2 * acc[j][i] - sqI[j];
                    if (key >= TJ[i]) {
                        int col = Ihalf + ty * 4 + j;
                        int pos = atomicAdd(&g_CNT[row], 1);
                        if (pos < CAP)
                            g_CAND[(size_t)row * CAP + pos] =
                                ((long long)key << 13) | (long long)(8191 - col);
                    }
                }
            }
        }
    }
}

// ======================= Phase 3: warp-per-row top-14 =======================
__global__ void select_topk() {
    int warp = threadIdx.x >> 5, lane = threadIdx.x & 31;
    int row  = blockIdx.x * 8 + warp;
    int cnt = g_CNT[row]; if (cnt > CAP) cnt = CAP;
    const long long* cand = g_CAND + (size_t)row * CAP;
    const long long MINV = 0x8000000000000000LL;

    long long bk[KNBR];
    #pragma unroll
    for (int s = 0; s < KNBR; s++) bk[s] = MINV;
    for (int c = lane; c < cnt; c += 32) {
        long long v = cand[c];
        if (v > bk[KNBR - 1]) {
            long long cv = v;
            #pragma unroll
            for (int s = 0; s < KNBR; s++)
                if (cv > bk[s]) { long long tf = bk[s]; bk[s] = cv; cv = tf; }
        }
    }
    for (int r = 0; r < KNBR; r++) {
        long long m = bk[0];
        int owner = lane;
        #pragma unroll
        for (int off = 16; off; off >>= 1) {
            long long ov = __shfl_xor_sync(0xffffffffu, m, off);
            int       ow = __shfl_xor_sync(0xffffffffu, owner, off);
            if (ov > m) { m = ov; owner = ow; }
        }
        if (lane == owner) {
            #pragma unroll
            for (int s = 0; s < KNBR - 1; s++) bk[s] = bk[s + 1];
            bk[KNBR - 1] = MINV;
        }
        if (lane == 0) g_NBR[row * KNBR + r] = 8191 - (int)(m & 8191);
    }
}

// ---------------- bulk lo-dim loss: exact triangular grid ----------------
__global__ void bulk_kernel(const float* __restrict__ LO) {
    int b = blockIdx.x;
    int i = (int)(32.5f - f_sqrt(32.5f * 32.5f - 2.0f * (float)b));
    while ((i + 1) * 32 - ((i + 1) * i) / 2 <= b) i++;
    while (i * 32 - (i * (i - 1)) / 2 > b) i--;
    int j = i + (b - (i * 32 - (i * (i - 1)) / 2));
    int ibase = i * 256, jbase = j * 256;

    __shared__ float2 sLo[256];
    __shared__ double sred[256];
    int tid = threadIdx.x;
    const float2* lo2 = (const float2*)LO;
    int gi = ibase + tid;
    float2 me = lo2[gi];
    sLo[tid] = lo2[jbase + tid];
    __syncthreads();

    float accf = 0.f;
    if (j > i) {
        #pragma unroll 4
        for (int c = 0; c < 256; c++) {
            float2 o = sLo[c];
            float dx = me.x - o.x, dy = me.y - o.y;
            float d = f_sqrt(fmaf(dx, dx, dy * dy));
            float r = f_rcp(1.0f + d);
            accf += f_lg2((1.0f - r) + 1e-10f);
        }
        accf *= 2.0f;
    } else {
        #pragma unroll 4
        for (int c = 0; c < 256; c++) {
            int jg = jbase + c;
            float2 o = sLo[c];
            float dx = me.x - o.x, dy = me.y - o.y;
            float d = f_sqrt(fmaf(dx, dx, dy * dy));
            float r = f_rcp(1.0f + d);
            float term = f_lg2((1.0f - r) + 1e-10f);
            float w = (jg > gi) ? 2.0f : ((jg == gi) ? 1.0f : 0.0f);
            accf += w * term;
        }
    }
    sred[tid] = (double)(accf * LN2F);
    __syncthreads();
    for (int off = 128; off; off >>= 1) { if (tid < off) sred[tid] += sred[tid + off]; __syncthreads(); }
    if (tid == 0) g_pb[b] = sred[0];
}

// ---------------- exact neighbor correction ----------------
__global__ void corr_kernel(const float* __restrict__ X, const float* __restrict__ LO) {
    __shared__ double wsum[8];
    int warp = threadIdx.x >> 5, lane = threadIdx.x & 31;
    int row  = blockIdx.x * 8 + warp;
    const float* xi = X + (size_t)row * DIMS;
    float a0 = xi[lane], a1 = xi[lane + 32], a2 = xi[lane + 64], a3 = xi[lane + 96];
    const float2* lo2 = (const float2*)LO;
    float2 li = lo2[row];
    float sqi = g_SQ[row];

    float acc = 0.f;
    for (int n = 0; n < KNBR; n++) {
        int j = g_NBR[row * KNBR + n];
        const float* xj = X + (size_t)j * DIMS;
        float dot = a0 * xj[lane] + a1 * xj[lane + 32] + a2 * xj[lane + 64] + a3 * xj[lane + 96];
        #pragma unroll
        for (int off = 16; off; off >>= 1) dot += __shfl_xor_sync(0xffffffffu, dot, off);
        float d2h = fmaxf(sqi + g_SQ[j] - 2.f * dot, 0.f);
        float hd = f_sqrt(d2h);
        float hs = f_ex2(-LOG2EF * hd);
        float2 lj = lo2[j];
        float dx = li.x - lj.x, dy = li.y - lj.y;
        float ld = f_sqrt(fmaf(dx, dx, dy * dy));
        float r  = f_rcp(1.0f + ld);
        float A  = hs * (f_lg2(r + 1e-10f) * LN2F);
        float Bs = f_lg2((1.0f - r) + 1e-10f) * LN2F;
        acc += (A - Bs);
    }
    if (lane == 0) wsum[warp] = (double)acc;
    __syncthreads();
    if (threadIdx.x == 0) {
        double s = 0;
        for (int k = 0; k < 8; k++) s += wsum[k];
        g_pc[blockIdx.x] = s;
    }
}

// ---------------- deterministic final reduce ----------------
__global__ void final_kernel(float* __restrict__ out) {
    __shared__ double sred[256];
    int t = threadIdx.x;
    double s = 0;
    for (int k = t; k < 528;  k += 256) s += g_pb[k];
    for (int k = t; k < 1024; k += 256) s += g_pc[k];
    sred[t] = s;
    __syncthreads();
    for (int off = 128; off; off >>= 1) { if (t < off) sred[t] += sred[t + off]; __syncthreads(); }
    if (t == 0) out[0] = (float)(-(sred[0] / 67108864.0) * 100.0);
}

// ---------------- launch: bulk forked onto a side stream, joined before final ----------------
extern "C" void kernel_launch(void* const* d_in, const int* in_sizes, int n_in,
                              void* d_out, int out_size) {
    const float* X; const float* LO;
    if (in_sizes[0] == N_PTS * DIMS) { X = (const float*)d_in[0]; LO = (const float*)d_in[1]; }
    else                             { X = (const float*)d_in[1]; LO = (const float*)d_in[0]; }

    cudaFuncSetAttribute(thresh_kernel, cudaFuncAttributeMaxDynamicSharedMemorySize, T_TOT);

    cudaStream_t s2;
    cudaEvent_t eFork, eJoin;
    cudaStreamCreateWithFlags(&s2, cudaStreamNonBlocking);
    cudaEventCreateWithFlags(&eFork, cudaEventDisableTiming);
    cudaEventCreateWithFlags(&eJoin, cudaEventDisableTiming);

    prep_kernel  <<<N_PTS / 8, 256>>>(X);

    cudaEventRecord(eFork, 0);
    cudaStreamWaitEvent(s2, eFork, 0);
    bulk_kernel  <<<NBULK, 256, 0, s2>>>(LO);

    thresh_kernel<<<128, 256, T_TOT>>>();
    filter_kernel<<<NPAIR * 4, 256>>>();
    select_topk  <<<N_PTS / 8, 256>>>();
    corr_kernel  <<<N_PTS / 8, 256>>>(X, LO);

    cudaEventRecord(eJoin, s2);
    cudaStreamWaitEvent(0, eJoin, 0);
    final_kernel <<<1, 256>>>((float*)d_out);

    cudaEventDestroy(eFork);
    cudaEventDestroy(eJoin);
    cudaStreamDestroy(s2);
}